// round 12
// baseline (speedup 1.0000x reference)
#include <cuda_runtime.h>
#include <cuda_bf16.h>
#include <math.h>
#include <stdint.h>

#define BB 512
#define TT 64
#define HH 512
#define VV 780
#define N_AT 40
#define KC 4
#define MAX_NB 8
#define NMSG (BB*TT+1)
#define BT (BB*TT)
#define NSTOP (BT+BB)
#define H2 (2*HH)
#define NBLK 128
#define ZROW (TT*BB)

// k_scan smem: Wz+Wh resident [512][32] + 4-stage ring (stage = 18432 B)
#define RING_STAGE_B 18432
#define SMEM_SCAN (2*512*32*4 + 4*RING_STAGE_B)   // 204800 B

// tgemm: 3-stage ring of (A[128][36] + B[32][132]) fp32 tiles
#define TG_ABUF (128*36)
#define TG_BBUF (32*132)
#define TG_STAGE (TG_ABUF + TG_BBUF)
#define SMEM_TG (3*TG_STAGE*4)

// ---------------- device scratch ----------------
// g_table / g_tableU are TIME-MAJOR: row (t*BB + b) holds message of (b, step t).
// Row ZROW is the permanent zero row (message id 0).
__device__ float g_table [NMSG*HH];
__device__ float g_tableU[NMSG*HH];
__device__ float g_nodeZ [BB*N_AT*HH];
__device__ float g_nodeR [BB*N_AT*HH];
__device__ float g_nodeH [BB*N_AT*HH];
__device__ float g_xall  [BT*HH];     // b-major (stop head)
__device__ float g_rootx [BB*HH];
__device__ float g_Xz    [BT*HH];     // TIME-MAJOR [T][B][H]
__device__ float g_Xr    [BT*HH];     // TIME-MAJOR
__device__ float g_Xh    [BT*HH];     // TIME-MAJOR
__device__ float g_sumh  [BB*HH];
__device__ float g_sumg  [BB*HH];
__device__ float g_stopA [NSTOP*H2];
__device__ float g_predH [BT*HH];
__device__ float g_predS [BT*VV];     // TIME-MAJOR rows (slot j = t*BB+b)
__device__ float g_score [NSTOP];
__device__ float g_red   [8];
__device__ unsigned g_flags[NBLK];

__device__ __forceinline__ float sigf(float x){ return 1.f/(1.f+expf(-x)); }

__device__ __forceinline__ void cp_async16(uint32_t dst, const void* src){
    asm volatile("cp.async.cg.shared.global [%0], [%1], 16;\n" :: "r"(dst), "l"(src));
}
__device__ __forceinline__ void cp_async16z(uint32_t dst, const void* src, int bytes){
    asm volatile("cp.async.cg.shared.global [%0], [%1], 16, %2;\n" :: "r"(dst), "l"(src), "r"(bytes));
}
__device__ __forceinline__ void cp_commit(){ asm volatile("cp.async.commit_group;\n"); }
template<int N> __device__ __forceinline__ void cp_wait(){ asm volatile("cp.async.wait_group %0;\n" :: "n"(N)); }

__device__ __forceinline__ void mma_tf32(float* d, const uint32_t* a, const uint32_t* b){
    asm volatile(
        "mma.sync.aligned.m16n8k8.row.col.f32.tf32.tf32.f32 "
        "{%0,%1,%2,%3},{%4,%5,%6,%7},{%8,%9},{%0,%1,%2,%3};\n"
        : "+f"(d[0]), "+f"(d[1]), "+f"(d[2]), "+f"(d[3])
        : "r"(a[0]), "r"(a[1]), "r"(a[2]), "r"(a[3]), "r"(b[0]), "r"(b[1]));
}

// map message id -> time-major row
__device__ __forceinline__ int id2row(int id){
    int j = id - 1;
    return id ? ((j & 63)*BB + (j >> 6)) : ZROW;
}

// ---------------- x features ----------------
__global__ void k_xfeat(const float* __restrict__ node_rep,
                        const int* __restrict__ cidx,
                        const int* __restrict__ rcidx)
{
    int i = blockIdx.x; int c = threadIdx.x;
    if (i < BT) {
        int b = i / TT;
        const int* ci = cidx + (size_t)i*KC;
        float s0=0.f, s1=0.f;
        #pragma unroll
        for (int k=0;k<KC;k++){
            const float* nr = node_rep + ((size_t)b*N_AT + ci[k])*HH;
            s0 += nr[c]; s1 += nr[c+256];
        }
        g_xall[(size_t)i*HH + c]       = s0;
        g_xall[(size_t)i*HH + c + 256] = s1;
    } else {
        int b = i - BT;
        const int* ci = rcidx + (size_t)b*KC;
        float s0=0.f, s1=0.f;
        #pragma unroll
        for (int k=0;k<KC;k++){
            const float* nr = node_rep + ((size_t)b*N_AT + ci[k])*HH;
            s0 += nr[c]; s1 += nr[c+256];
        }
        g_rootx[b*HH + c]       = s0;
        g_rootx[b*HH + c + 256] = s1;
    }
}

// ---------------- gather node projections (writes TIME-MAJOR X arrays) ----------------
__global__ void k_xproj(const int* __restrict__ cidx,
                        const float* __restrict__ bz,
                        const float* __restrict__ br,
                        const float* __restrict__ bh)
{
    int i = blockIdx.x;
    int b = i / TT, t = i % TT;
    const int* ci = cidx + (size_t)i*KC;
    int r0 = b*N_AT;
    #pragma unroll
    for (int cc=0; cc<2; cc++){
        int c = threadIdx.x + cc*256;
        float sz = bz[c], sr = br[c], sh = bh[c];
        #pragma unroll
        for (int k=0;k<KC;k++){
            size_t row = (size_t)(r0 + ci[k])*HH + c;
            sz += g_nodeZ[row];
            sr += g_nodeR[row];
            sh += g_nodeH[row];
        }
        size_t o = ((size_t)t*BB + b)*HH + c;
        g_Xz[o] = sz;
        g_Xr[o] = sr;
        g_Xh[o] = sh;
    }
}

// ---------------- tf32 tensor-core GEMM ----------------
template<int EPI, bool NG, bool ZSEL>
__global__ void __launch_bounds__(256)
tgemm(const float* __restrict__ A, int lda,
      const float* __restrict__ Bm0, int ldb,
      const float* __restrict__ bias,
      float* __restrict__ C0, int ldc,
      int N, int K,
      const float* __restrict__ us,
      const float* Bm1, const float* Bm2,
      float* C1, float* C2)
{
    extern __shared__ float dynsm[];
    const int tid  = threadIdx.x;
    const int warp = tid >> 5, lane = tid & 31;
    const int wm = warp & 3, wn = warp >> 2;
    const int gid = lane >> 2, tig = lane & 3;
    const int by = blockIdx.y, bx = blockIdx.x;
    const int rowb = by*128, colb = bx*128;

    const float* Bm = Bm0;
    float* C = C0;
    if (ZSEL){
        if (blockIdx.z == 1){ Bm = Bm1; C = C1; }
        else if (blockIdx.z == 2){ Bm = Bm2; C = C2; }
    }

    const int aq0 = tid;
    const int bq0 = tid;

    uint32_t smem_base = (uint32_t)__cvta_generic_to_shared(dynsm);

    float acc[2][8][4];
    #pragma unroll
    for (int mt=0;mt<2;mt++)
        #pragma unroll
        for (int nt=0;nt<8;nt++)
            #pragma unroll
            for (int i=0;i<4;i++) acc[mt][nt][i]=0.f;

    const int nk = K >> 5;

    auto issue = [&](int kt, int stage){
        uint32_t sa = smem_base + stage*TG_STAGE*4;
        uint32_t sb = sa + TG_ABUF*4;
        #pragma unroll
        for (int i=0;i<4;i++){
            int q = aq0 + 256*i;
            int r = q >> 3, k4 = (q & 7)*4;
            cp_async16(sa + (r*36 + k4)*4, A + (size_t)(rowb + r)*lda + kt*32 + k4);
        }
        #pragma unroll
        for (int i=0;i<4;i++){
            int q = bq0 + 256*i;
            int kr = q >> 5, n4 = (q & 31)*4;
            uint32_t dst = sb + (kr*132 + n4)*4;
            if (NG){
                int col = colb + n4;
                int bytes = (col + 3 < N) ? 16 : ((col < N) ? (N - col)*4 : 0);
                const float* src = Bm + (size_t)(kt*32 + kr)*ldb + (bytes ? col : 0);
                cp_async16z(dst, src, bytes);
            } else {
                cp_async16(dst, Bm + (size_t)(kt*32 + kr)*ldb + colb + n4);
            }
        }
        cp_commit();
    };

    issue(0, 0);
    if (nk > 1) issue(1, 1);

    for (int it=0; it<nk; it++){
        if (it+2 < nk) issue(it+2, (it+2)%3);
        if (it+1 < nk) cp_wait<1>(); else cp_wait<0>();
        __syncthreads();

        const uint32_t* As = (const uint32_t*)(dynsm + (it%3)*TG_STAGE);
        const uint32_t* Bs = (const uint32_t*)(dynsm + (it%3)*TG_STAGE + TG_ABUF);

        #pragma unroll
        for (int ks=0; ks<4; ks++){
            uint32_t af[2][4];
            #pragma unroll
            for (int mt=0; mt<2; mt++){
                int r = wm*32 + mt*16 + gid;
                af[mt][0] = As[r*36 + ks*8 + tig];
                af[mt][1] = As[(r+8)*36 + ks*8 + tig];
                af[mt][2] = As[r*36 + ks*8 + tig + 4];
                af[mt][3] = As[(r+8)*36 + ks*8 + tig + 4];
            }
            uint32_t bf[8][2];
            #pragma unroll
            for (int nt=0; nt<8; nt++){
                int n = wn*64 + nt*8 + gid;
                bf[nt][0] = Bs[(ks*8 + tig)*132 + n];
                bf[nt][1] = Bs[(ks*8 + tig + 4)*132 + n];
            }
            #pragma unroll
            for (int mt=0; mt<2; mt++)
                #pragma unroll
                for (int nt=0; nt<8; nt++)
                    mma_tf32(acc[mt][nt], af[mt], bf[nt]);
        }
        __syncthreads();
    }

    if (EPI == 2){
        #pragma unroll
        for (int mt=0; mt<2; mt++){
            float s0 = 0.f, s1 = 0.f;
            #pragma unroll
            for (int nt=0; nt<8; nt++){
                int col = colb + wn*64 + nt*8 + 2*tig;
                float b0 = bias[col], b1 = bias[col+1];
                float u0 = us[col],  u1 = us[col+1];
                float v;
                v = acc[mt][nt][0] + b0; s0 += (v>0.f? v:0.f)*u0;
                v = acc[mt][nt][1] + b1; s0 += (v>0.f? v:0.f)*u1;
                v = acc[mt][nt][2] + b0; s1 += (v>0.f? v:0.f)*u0;
                v = acc[mt][nt][3] + b1; s1 += (v>0.f? v:0.f)*u1;
            }
            s0 += __shfl_xor_sync(0xffffffffu, s0, 1);
            s0 += __shfl_xor_sync(0xffffffffu, s0, 2);
            s1 += __shfl_xor_sync(0xffffffffu, s1, 1);
            s1 += __shfl_xor_sync(0xffffffffu, s1, 2);
            if (tig == 0){
                int row = rowb + wm*32 + mt*16 + gid;
                atomicAdd(&g_score[row], s0);
                atomicAdd(&g_score[row+8], s1);
            }
        }
    } else {
        #pragma unroll
        for (int mt=0; mt<2; mt++){
            #pragma unroll
            for (int nt=0; nt<8; nt++){
                int col = colb + wn*64 + nt*8 + 2*tig;
                int row = rowb + wm*32 + mt*16 + gid;
                #pragma unroll
                for (int i=0; i<4; i++){
                    int cc = col + (i & 1);
                    int rr = row + ((i >> 1) ? 8 : 0);
                    if (!NG || cc < N){
                        float v = acc[mt][nt][i];
                        if (EPI != 3) v += bias[cc];
                        if (EPI == 1) v = v > 0.f ? v : 0.f;
                        C[(size_t)rr*ldc + cc] = v;
                    }
                }
            }
        }
    }
}

// ---------------- persistent scan kernel ----------------
// Flag-array grid barrier: one uncontended store per CTA (after a single
// release fence), 128 threads each spin on one flag. No atomic serialization.
__device__ __forceinline__ void gsync(int& epoch)
{
    __syncthreads();
    if (threadIdx.x == 0){
        __threadfence();
        ((volatile unsigned*)g_flags)[blockIdx.x] = (unsigned)epoch;
    }
    if (threadIdx.x < NBLK){
        while (((volatile unsigned*)g_flags)[threadIdx.x] < (unsigned)epoch) { }
    }
    epoch++;
    __syncthreads();
}

__global__ void __launch_bounds__(256, 1)
k_scan(const int* __restrict__ nei_h,
       const float* __restrict__ Wzh,
       const float* __restrict__ Whh,
       const float* __restrict__ Ur)
{
    extern __shared__ float smem[];
    float* Wz_s = smem;                    // [512][32] swizzled
    float* Wh_s = Wz_s + 512*32;
    float* ringf = Wh_s + 512*32;          // 4 stages x 4608 floats

    const int tid = threadIdx.x;
    const int blk = blockIdx.x;
    const int rt = blk >> 4, ct = blk & 15;     // 8 row tiles x 16 col tiles
    const int r0 = rt*64, c0 = ct*32;
    const int warp = tid >> 5, lane = tid & 31;
    const int wm = warp & 3, wn = warp >> 2;    // warp tile 16x16
    const int gid = lane >> 2, tig = lane & 3;
    const int id4a = tid*2, id4b = tid*2+1;
    const int sra = id4a >> 3, ska = (id4a & 7)*4;
    const int srb = id4b >> 3, skb = (id4b & 7)*4;
    const int ur_r = tid >> 3, ur_c = (tid & 7)*4;   // Ur chunk staging [32][40]

    const uint32_t ring_u = (uint32_t)__cvta_generic_to_shared(ringf);

    for (int idx = tid; idx < 512*32; idx += 256){
        int k = idx >> 5; int cc = idx & 31;
        int sw = cc ^ ((k & 3) << 3);
        Wz_s[k*32 + sw] = Wzh[(size_t)k*HH + c0 + cc];
        Wh_s[k*32 + sw] = Whh[(size_t)k*HH + c0 + cc];
    }
    __syncthreads();

    const uint32_t* Wz32 = (const uint32_t*)Wz_s;
    const uint32_t* Wh32 = (const uint32_t*)Wh_s;

    int epoch = 1;

    for (int t = 0; t < TT; t++){
        const size_t slab = (size_t)t*BB;   // time-major row base for this step

        // ---- phase A: gather sum_h, sum_g ----
        #pragma unroll
        for (int rb=0; rb<4; rb++){
            int b = blk*4 + rb;
            const int* idx = nei_h + ((size_t)b*TT + t)*MAX_NB;
            int ii[8];
            #pragma unroll
            for (int n=0;n<8;n++) ii[n] = id2row(idx[n]);
            #pragma unroll
            for (int cc=0; cc<2; cc++){
                int ch = tid + cc*256;
                float xr = g_Xr[(slab + b)*HH + ch];
                float ah=0.f, ag=0.f;
                #pragma unroll
                for (int n=0;n<8;n++){
                    size_t base = (size_t)ii[n]*HH + ch;
                    float hv = __ldcg(&g_table[base]);
                    float uv = __ldcg(&g_tableU[base]);
                    ah += hv;
                    ag += hv * sigf(xr + uv);
                }
                g_sumh[b*HH+ch] = ah;
                g_sumg[b*HH+ch] = ag;
            }
        }
        gsync(epoch);

        // ---- phase B: dual tf32 GEMM (4-stage cp.async ring) + GRU epilogue ----
        {
            float accz[2][4], acch[2][4];
            #pragma unroll
            for (int nt=0;nt<2;nt++)
                #pragma unroll
                for (int i=0;i<4;i++){ accz[nt][i]=0.f; acch[nt][i]=0.f; }

            auto issueB = [&](int chk){
                uint32_t sa = ring_u + (chk & 3)*RING_STAGE_B;
                cp_async16(sa + (sra*36+ska)*4, &g_sumh[(size_t)(r0+sra)*HH + chk*32 + ska]);
                cp_async16(sa + (srb*36+skb)*4, &g_sumh[(size_t)(r0+srb)*HH + chk*32 + skb]);
                cp_async16(sa + 9216 + (sra*36+ska)*4, &g_sumg[(size_t)(r0+sra)*HH + chk*32 + ska]);
                cp_async16(sa + 9216 + (srb*36+skb)*4, &g_sumg[(size_t)(r0+srb)*HH + chk*32 + skb]);
                cp_commit();
            };
            issueB(0); issueB(1); issueB(2);

            for (int chk=0; chk<16; chk++){
                if (chk < 14) cp_wait<2>(); else if (chk == 14) cp_wait<1>(); else cp_wait<0>();
                __syncthreads();
                if (chk+3 < 16) issueB(chk+3);

                const uint32_t* Ah = (const uint32_t*)(ringf + (chk & 3)*4608);
                const uint32_t* Ag = Ah + 2304;

                #pragma unroll
                for (int ks=0; ks<4; ks++){
                    int rb0 = wm*16 + gid;
                    uint32_t ah[4], ag[4];
                    ah[0]=Ah[rb0*36 + ks*8 + tig];     ah[1]=Ah[(rb0+8)*36 + ks*8 + tig];
                    ah[2]=Ah[rb0*36 + ks*8 + tig + 4]; ah[3]=Ah[(rb0+8)*36 + ks*8 + tig + 4];
                    ag[0]=Ag[rb0*36 + ks*8 + tig];     ag[1]=Ag[(rb0+8)*36 + ks*8 + tig];
                    ag[2]=Ag[rb0*36 + ks*8 + tig + 4]; ag[3]=Ag[(rb0+8)*36 + ks*8 + tig + 4];
                    int kg = chk*32 + ks*8;
                    #pragma unroll
                    for (int nt=0; nt<2; nt++){
                        int n = wn*16 + nt*8 + gid;
                        int nsw = n ^ (tig << 3);
                        uint32_t bz[2], bh[2];
                        bz[0] = Wz32[(kg+tig)*32 + nsw];
                        bz[1] = Wz32[(kg+tig+4)*32 + nsw];
                        bh[0] = Wh32[(kg+tig)*32 + nsw];
                        bh[1] = Wh32[(kg+tig+4)*32 + nsw];
                        mma_tf32(accz[nt], ah, bz);
                        mma_tf32(acch[nt], ag, bh);
                    }
                }
            }

            #pragma unroll
            for (int nt=0; nt<2; nt++){
                #pragma unroll
                for (int half=0; half<2; half++){
                    int b   = r0 + wm*16 + gid + half*8;
                    int col = c0 + wn*16 + nt*8 + tig*2;
                    size_t xi = (slab + b)*HH + col;
                    float2 xz = *(const float2*)&g_Xz[xi];
                    float2 xh = *(const float2*)&g_Xh[xi];
                    float2 sh = __ldcg((const float2*)&g_sumh[(size_t)b*HH + col]);
                    float z0 = sigf(xz.x + accz[nt][half*2+0]);
                    float z1 = sigf(xz.y + accz[nt][half*2+1]);
                    float p0 = tanhf(xh.x + acch[nt][half*2+0]);
                    float p1 = tanhf(xh.y + acch[nt][half*2+1]);
                    float2 out;
                    out.x = (1.f - z0)*sh.x + z0*p0;
                    out.y = (1.f - z1)*sh.y + z1*p1;
                    *(float2*)&g_table[xi] = out;
                }
            }
        }
        gsync(epoch);

        if (t == TT-1) break;

        // ---- phase C: tableU(step-t rows) = new_h @ Ur (contiguous slab) ----
        {
            float accu[2][4];
            #pragma unroll
            for (int nt=0;nt<2;nt++)
                #pragma unroll
                for (int i=0;i<4;i++) accu[nt][i]=0.f;

            auto issueC = [&](int chk){
                uint32_t sa = ring_u + (chk & 3)*RING_STAGE_B;
                cp_async16(sa + (sra*36+ska)*4, &g_table[(slab + r0+sra)*HH + chk*32 + ska]);
                cp_async16(sa + (srb*36+skb)*4, &g_table[(slab + r0+srb)*HH + chk*32 + skb]);
                cp_async16(sa + 9216 + (ur_r*40 + ur_c)*4, &Ur[(size_t)(chk*32 + ur_r)*HH + c0 + ur_c]);
                cp_commit();
            };
            issueC(0); issueC(1); issueC(2);

            for (int chk=0; chk<16; chk++){
                if (chk < 14) cp_wait<2>(); else if (chk == 14) cp_wait<1>(); else cp_wait<0>();
                __syncthreads();
                if (chk+3 < 16) issueC(chk+3);

                const uint32_t* Ah = (const uint32_t*)(ringf + (chk & 3)*4608);
                const uint32_t* Uc = Ah + 2304;   // [32][40]

                #pragma unroll
                for (int ks=0; ks<4; ks++){
                    int rb0 = wm*16 + gid;
                    uint32_t ah[4];
                    ah[0]=Ah[rb0*36 + ks*8 + tig];     ah[1]=Ah[(rb0+8)*36 + ks*8 + tig];
                    ah[2]=Ah[rb0*36 + ks*8 + tig + 4]; ah[3]=Ah[(rb0+8)*36 + ks*8 + tig + 4];
                    #pragma unroll
                    for (int nt=0; nt<2; nt++){
                        int n = wn*16 + nt*8 + gid;
                        uint32_t bu[2];
                        bu[0] = Uc[(ks*8 + tig)*40 + n];
                        bu[1] = Uc[(ks*8 + tig + 4)*40 + n];
                        mma_tf32(accu[nt], ah, bu);
                    }
                }
            }

            #pragma unroll
            for (int nt=0; nt<2; nt++){
                #pragma unroll
                for (int half=0; half<2; half++){
                    int b   = r0 + wm*16 + gid + half*8;
                    int col = c0 + wn*16 + nt*8 + tig*2;
                    float2 out;
                    out.x = accu[nt][half*2+0];
                    out.y = accu[nt][half*2+1];
                    *(float2*)&g_tableU[(slab + b)*HH + col] = out;
                }
            }
        }
        gsync(epoch);
    }
}

// ---------------- deferred o gather + concat into stopA ----------------
__global__ void k_oall(const int* __restrict__ nei_o, const int* __restrict__ root_nei)
{
    int i = blockIdx.x;
    int c = blockIdx.y*256 + threadIdx.x;
    if (i < BT) {
        int tt = i % TT;
        float xv = g_xall[(size_t)i*HH + c];
        const int* idx = nei_o + (size_t)i*MAX_NB;
        float o = 0.f;
        #pragma unroll
        for (int n=0;n<MAX_NB;n++){
            int id = idx[n];
            if (id > 0 && ((id-1) & 63) < tt){
                int j = id - 1;
                o += g_table[(size_t)((j & 63)*BB + (j >> 6))*HH + c];
            }
        }
        g_stopA[(size_t)i*H2 + c]      = xv;
        g_stopA[(size_t)i*H2 + HH + c] = o;
    } else {
        int b = i - BT;
        float xv = g_rootx[b*HH + c];
        const int* idx = root_nei + (size_t)b*MAX_NB;
        float o = 0.f;
        #pragma unroll
        for (int n=0;n<MAX_NB;n++){
            int id = idx[n];
            int j = id - 1;
            size_t row = id ? (size_t)((j & 63)*BB + (j >> 6)) : (size_t)ZROW;
            o += g_table[row*HH + c];
        }
        g_stopA[(size_t)i*H2 + c]      = xv;
        g_stopA[(size_t)i*H2 + HH + c] = o;
    }
}

// ---------------- stop loss / acc ----------------
__global__ void k_stoploss(const int* __restrict__ direction, const float* __restrict__ usb)
{
    int i = blockIdx.x*256 + threadIdx.x;
    float li = 0.f, ci = 0.f;
    if (i < NSTOP){
        float s = g_score[i] + usb[0];
        float tgt = (i < BT) ? (float)direction[i] : 0.f;
        float sp = (s > 0.f) ? (s + log1pf(expf(-s))) : log1pf(expf(s));
        li = sp - s*tgt;
        float pred = (s >= 0.f) ? 1.f : 0.f;
        ci = (pred == tgt) ? 1.f : 0.f;
    }
    __shared__ float rl[256], rc[256];
    rl[threadIdx.x]=li; rc[threadIdx.x]=ci;
    __syncthreads();
    for (int st=128; st>0; st>>=1){
        if (threadIdx.x < st){ rl[threadIdx.x]+=rl[threadIdx.x+st]; rc[threadIdx.x]+=rc[threadIdx.x+st]; }
        __syncthreads();
    }
    if (threadIdx.x==0){
        atomicAdd(&g_red[3], rl[0]);
        atomicAdd(&g_red[4], rc[0]);
    }
}

// ---------------- pred head CE / acc (rows are TIME-MAJOR slots) ----------------
__global__ void k_ce(const int* __restrict__ direction, const int* __restrict__ target)
{
    int jrow = blockIdx.x;                   // slot = t*BB + b
    int i = (jrow % BB)*TT + (jrow / BB);    // logical b*T + t
    int t = threadIdx.x;
    const float* S = g_predS + (size_t)jrow*VV;
    float val[4];
    float lmax = -1e30f; int lidx = 0;
    #pragma unroll
    for (int r=0;r<4;r++){
        int v = t + 256*r;
        if (v < VV){
            float x = S[v];
            val[r] = x;
            if (x > lmax){ lmax = x; lidx = v; }
        } else val[r] = -1e30f;
    }
    __shared__ float smax[256]; __shared__ int sidx[256];
    smax[t]=lmax; sidx[t]=lidx;
    __syncthreads();
    for (int st=128; st>0; st>>=1){
        if (t < st){
            float o = smax[t+st]; int oi = sidx[t+st];
            if (o > smax[t] || (o == smax[t] && oi < sidx[t])){ smax[t]=o; sidx[t]=oi; }
        }
        __syncthreads();
    }
    float m = smax[0]; int am = sidx[0];
    __syncthreads();
    float se = 0.f;
    #pragma unroll
    for (int r=0;r<4;r++){
        int v = t + 256*r;
        if (v < VV) se += expf(val[r] - m);
    }
    __shared__ float ssum[256];
    ssum[t]=se;
    __syncthreads();
    for (int st=128; st>0; st>>=1){
        if (t < st) ssum[t]+=ssum[t+st];
        __syncthreads();
    }
    if (t==0){
        float lse = m + logf(ssum[0]);
        int tg = target[i];
        float ce = lse - S[tg];
        float msk = (direction[i]==1) ? 1.f : 0.f;
        atomicAdd(&g_red[0], ce*msk);
        atomicAdd(&g_red[1], (am==tg) ? msk : 0.f);
        atomicAdd(&g_red[2], msk);
    }
}

__global__ void k_final(float* out)
{
    out[0] = g_red[0] / (float)BB;
    out[1] = g_red[3] / (float)BB;
    out[2] = g_red[1] / g_red[2];
    out[3] = g_red[4] / (float)NSTOP;
}

// ---------------- host launch ----------------
extern "C" void kernel_launch(void* const* d_in, const int* in_sizes, int n_in,
                              void* d_out, int out_size)
{
    const float* node_rep = (const float*)d_in[0];
    const int*   clique   = (const int*)  d_in[1];
    const int*   rclique  = (const int*)  d_in[2];
    const int*   nei_h    = (const int*)  d_in[3];
    const int*   nei_o    = (const int*)  d_in[4];
    const int*   rnei     = (const int*)  d_in[5];
    const int*   dir      = (const int*)  d_in[6];
    const int*   ptgt     = (const int*)  d_in[7];
    const float* Wz  = (const float*)d_in[8];
    const float* Wzb = (const float*)d_in[9];
    const float* Wr  = (const float*)d_in[10];
    const float* Wrb = (const float*)d_in[11];
    const float* Ur  = (const float*)d_in[12];
    const float* Wh  = (const float*)d_in[13];
    const float* Whb = (const float*)d_in[14];
    const float* Ww  = (const float*)d_in[15];
    const float* Wwb = (const float*)d_in[16];
    const float* Uw  = (const float*)d_in[17];
    const float* Ub  = (const float*)d_in[18];
    const float* Wo  = (const float*)d_in[19];
    const float* Wob = (const float*)d_in[20];
    const float* Us  = (const float*)d_in[21];
    const float* Usb = (const float*)d_in[22];

    float *tb, *tbU, *nZ, *nR, *nH, *stopA, *predH, *predS, *score, *red;
    unsigned* flags;
    cudaGetSymbolAddress((void**)&tb,    g_table);
    cudaGetSymbolAddress((void**)&tbU,   g_tableU);
    cudaGetSymbolAddress((void**)&nZ,    g_nodeZ);
    cudaGetSymbolAddress((void**)&nR,    g_nodeR);
    cudaGetSymbolAddress((void**)&nH,    g_nodeH);
    cudaGetSymbolAddress((void**)&stopA, g_stopA);
    cudaGetSymbolAddress((void**)&predH, g_predH);
    cudaGetSymbolAddress((void**)&predS, g_predS);
    cudaGetSymbolAddress((void**)&score, g_score);
    cudaGetSymbolAddress((void**)&red,   g_red);
    cudaGetSymbolAddress((void**)&flags, g_flags);

    static int attr_set = 0;
    if (!attr_set){
        cudaFuncSetAttribute(k_scan, cudaFuncAttributeMaxDynamicSharedMemorySize, SMEM_SCAN);
        cudaFuncSetAttribute(tgemm<3,false,true>,  cudaFuncAttributeMaxDynamicSharedMemorySize, SMEM_TG);
        cudaFuncSetAttribute(tgemm<2,false,false>, cudaFuncAttributeMaxDynamicSharedMemorySize, SMEM_TG);
        cudaFuncSetAttribute(tgemm<1,false,false>, cudaFuncAttributeMaxDynamicSharedMemorySize, SMEM_TG);
        cudaFuncSetAttribute(tgemm<0,true,false>,  cudaFuncAttributeMaxDynamicSharedMemorySize, SMEM_TG);
        attr_set = 1;
    }

    cudaMemsetAsync(tb,   0, sizeof(float)*(size_t)NMSG*HH);
    cudaMemsetAsync(tbU,  0, sizeof(float)*(size_t)NMSG*HH);
    cudaMemsetAsync(score,0, sizeof(float)*NSTOP);
    cudaMemsetAsync(red,  0, sizeof(float)*8);
    cudaMemsetAsync(flags,0, sizeof(unsigned)*NBLK);

    // x features + node-level projections (tf32)
    k_xfeat<<<BT+BB, 256>>>(node_rep, clique, rclique);

    dim3 gN(4, (BB*N_AT)/128, 3);
    tgemm<3,false,true><<<gN, 256, SMEM_TG>>>(node_rep, HH, Wz, HH, nullptr, nZ, HH,
                                              HH, HH, nullptr, Wr, Wh, nR, nH);
    k_xproj<<<BT, 256>>>(clique, Wzb, Wrb, Whb);

    // sequential scan: persistent kernel, tf32 mma, cp.async rings, time-major state
    const float* Wzh = Wz + (size_t)HH*HH;
    const float* Whh = Wh + (size_t)HH*HH;
    k_scan<<<NBLK, 256, SMEM_SCAN>>>(nei_h, Wzh, Whh, Ur);

    // stop head (tf32, fused relu+dot epilogue)
    k_oall<<<dim3(NSTOP,2), 256>>>(nei_o, rnei);
    tgemm<2,false,false><<<dim3(4, NSTOP/128), 256, SMEM_TG>>>(stopA, H2, Uw, HH, Ub,
                                                               nullptr, 0, HH, H2, Us,
                                                               nullptr, nullptr, nullptr, nullptr);
    k_stoploss<<<NSTOP/256, 256>>>(dir, Usb);

    // pred head (tf32) — A rows are time-major slots 0..BT-1
    tgemm<1,false,false><<<dim3(4, BT/128), 256, SMEM_TG>>>(tb, HH, Ww, HH, Wwb,
                                                            predH, HH, HH, HH, nullptr,
                                                            nullptr, nullptr, nullptr, nullptr);
    tgemm<0,true,false><<<dim3(7, BT/128), 256, SMEM_TG>>>(predH, HH, Wo, VV, Wob,
                                                           predS, VV, VV, HH, nullptr,
                                                           nullptr, nullptr, nullptr, nullptr);
    k_ce<<<BT, 256>>>(dir, ptgt);

    k_final<<<1,1>>>((float*)d_out);
}

// round 13
// speedup vs baseline: 1.1904x; 1.1904x over previous
#include <cuda_runtime.h>
#include <cuda_bf16.h>
#include <math.h>
#include <stdint.h>

#define BB 512
#define TT 64
#define HH 512
#define VV 780
#define N_AT 40
#define KC 4
#define MAX_NB 8
#define NMSG (BB*TT+1)
#define BT (BB*TT)
#define NSTOP (BT+BB)
#define H2 (2*HH)
#define NBLK 128

// k_scan smem: Wz+Wh resident [512][32] + 4-stage ring (stage = 18432 B)
#define RING_STAGE_B 18432
#define SMEM_SCAN (2*512*32*4 + 4*RING_STAGE_B)   // 204800 B

// tgemm: 3-stage ring of (A[128][36] + B[32][132]) fp32 tiles
#define TG_ABUF (128*36)
#define TG_BBUF (32*132)
#define TG_STAGE (TG_ABUF + TG_BBUF)
#define SMEM_TG (3*TG_STAGE*4)

// ---------------- device scratch ----------------
__device__ float g_table [NMSG*HH];   // b-major: row b*TT+t+1
__device__ float g_tableU[NMSG*HH];
__device__ float g_nodeZ [BB*N_AT*HH];
__device__ float g_nodeR [BB*N_AT*HH];
__device__ float g_nodeH [BB*N_AT*HH];
__device__ float g_nodeS [BB*N_AT*HH];   // node_rep @ Uw_x
__device__ float g_Xz    [BT*HH];
__device__ float g_Xr    [BT*HH];
__device__ float g_Xh    [BT*HH];
__device__ float g_sumh  [BB*HH];
__device__ float g_sumg  [BB*HH];
__device__ float g_stopO [NSTOP*HH];     // o-half of stop features
__device__ float g_stopX [NSTOP*HH];     // gathered x@Uw_x (epilogue addend)
__device__ float g_predH [BT*HH];
__device__ float g_predS [BT*VV];
__device__ float g_score [NSTOP];
__device__ float g_red   [8];
__device__ unsigned g_bar;
__device__ int g_cnt;
__device__ int g_list[BT];

__device__ __forceinline__ float sigf(float x){ return 1.f/(1.f+expf(-x)); }

__device__ __forceinline__ void cp_async16(uint32_t dst, const void* src){
    asm volatile("cp.async.cg.shared.global [%0], [%1], 16;\n" :: "r"(dst), "l"(src));
}
__device__ __forceinline__ void cp_async16z(uint32_t dst, const void* src, int bytes){
    asm volatile("cp.async.cg.shared.global [%0], [%1], 16, %2;\n" :: "r"(dst), "l"(src), "r"(bytes));
}
__device__ __forceinline__ void cp_commit(){ asm volatile("cp.async.commit_group;\n"); }
template<int N> __device__ __forceinline__ void cp_wait(){ asm volatile("cp.async.wait_group %0;\n" :: "n"(N)); }

__device__ __forceinline__ void mma_tf32(float* d, const uint32_t* a, const uint32_t* b){
    asm volatile(
        "mma.sync.aligned.m16n8k8.row.col.f32.tf32.tf32.f32 "
        "{%0,%1,%2,%3},{%4,%5,%6,%7},{%8,%9},{%0,%1,%2,%3};\n"
        : "+f"(d[0]), "+f"(d[1]), "+f"(d[2]), "+f"(d[3])
        : "r"(a[0]), "r"(a[1]), "r"(a[2]), "r"(a[3]), "r"(b[0]), "r"(b[1]));
}

// ---------------- gather node projections into per-(b,t) arrays ----------------
__global__ void k_xproj(const int* __restrict__ cidx,
                        const float* __restrict__ bz,
                        const float* __restrict__ br,
                        const float* __restrict__ bh)
{
    int i = blockIdx.x;
    int b = i / TT;
    const int* ci = cidx + (size_t)i*KC;
    int r0 = b*N_AT;
    #pragma unroll
    for (int cc=0; cc<2; cc++){
        int c = threadIdx.x + cc*256;
        float sz = bz[c], sr = br[c], sh = bh[c], ss = 0.f;
        #pragma unroll
        for (int k=0;k<KC;k++){
            size_t row = (size_t)(r0 + ci[k])*HH + c;
            sz += g_nodeZ[row];
            sr += g_nodeR[row];
            sh += g_nodeH[row];
            ss += g_nodeS[row];
        }
        g_Xz[(size_t)i*HH + c] = sz;
        g_Xr[(size_t)i*HH + c] = sr;
        g_Xh[(size_t)i*HH + c] = sh;
        g_stopX[(size_t)i*HH + c] = ss;
    }
}

// root rows of stopX
__global__ void k_rootS(const int* __restrict__ rcidx)
{
    int b = blockIdx.x;
    const int* ci = rcidx + (size_t)b*KC;
    #pragma unroll
    for (int cc=0; cc<2; cc++){
        int c = threadIdx.x + cc*256;
        float ss = 0.f;
        #pragma unroll
        for (int k=0;k<KC;k++)
            ss += g_nodeS[(size_t)(b*N_AT + ci[k])*HH + c];
        g_stopX[(size_t)(BT + b)*HH + c] = ss;
    }
}

// compact indices with direction==1
__global__ void k_compact(const int* __restrict__ direction)
{
    int i = blockIdx.x*256 + threadIdx.x;
    if (i < BT && direction[i] == 1){
        int s = atomicAdd(&g_cnt, 1);
        g_list[s] = i;
    }
}

// ---------------- tf32 tensor-core GEMM ----------------
// EPI: 0 C=acc+bias ; 1 relu(acc+bias) ; 2 stop-head: relu(acc+bias+xadd) dot us ; 3 C=acc
// NG: guard N.  ZSEL: blockIdx.z selects from 4 (B,C) pairs.
// GMODE: 0 none ; 1 gather A rows via g_list + cnt early-exit ; 2 cnt early-exit only
template<int EPI, bool NG, bool ZSEL, int GMODE>
__global__ void __launch_bounds__(256)
tgemm(const float* __restrict__ A, int lda,
      const float* __restrict__ Bm0, int ldb,
      const float* __restrict__ bias,
      float* __restrict__ C0, int ldc,
      int N, int K,
      const float* __restrict__ us,
      const float* __restrict__ xadd,
      const float* Bm1, const float* Bm2, const float* Bm3,
      float* C1, float* C2, float* C3)
{
    extern __shared__ float dynsm[];
    const int by = blockIdx.y, bx = blockIdx.x;
    const int rowb = by*128, colb = bx*128;
    if (GMODE){ if (rowb >= g_cnt) return; }

    const int tid  = threadIdx.x;
    const int warp = tid >> 5, lane = tid & 31;
    const int wm = warp & 3, wn = warp >> 2;
    const int gid = lane >> 2, tig = lane & 3;

    const float* Bm = Bm0;
    float* C = C0;
    if (ZSEL){
        if (blockIdx.z == 1){ Bm = Bm1; C = C1; }
        else if (blockIdx.z == 2){ Bm = Bm2; C = C2; }
        else if (blockIdx.z == 3){ Bm = Bm3; C = C3; }
    }

    uint32_t smem_base = (uint32_t)__cvta_generic_to_shared(dynsm);

    float acc[2][8][4];
    #pragma unroll
    for (int mt=0;mt<2;mt++)
        #pragma unroll
        for (int nt=0;nt<8;nt++)
            #pragma unroll
            for (int i=0;i<4;i++) acc[mt][nt][i]=0.f;

    const int nk = K >> 5;

    auto issue = [&](int kt, int stage){
        uint32_t sa = smem_base + stage*TG_STAGE*4;
        uint32_t sb = sa + TG_ABUF*4;
        #pragma unroll
        for (int i=0;i<4;i++){
            int q = tid + 256*i;
            int r = q >> 3, k4 = (q & 7)*4;
            size_t arow = (GMODE == 1) ? (size_t)g_list[rowb + r] : (size_t)(rowb + r);
            cp_async16(sa + (r*36 + k4)*4, A + arow*lda + kt*32 + k4);
        }
        #pragma unroll
        for (int i=0;i<4;i++){
            int q = tid + 256*i;
            int kr = q >> 5, n4 = (q & 31)*4;
            uint32_t dst = sb + (kr*132 + n4)*4;
            if (NG){
                int col = colb + n4;
                int bytes = (col + 3 < N) ? 16 : ((col < N) ? (N - col)*4 : 0);
                const float* src = Bm + (size_t)(kt*32 + kr)*ldb + (bytes ? col : 0);
                cp_async16z(dst, src, bytes);
            } else {
                cp_async16(dst, Bm + (size_t)(kt*32 + kr)*ldb + colb + n4);
            }
        }
        cp_commit();
    };

    issue(0, 0);
    if (nk > 1) issue(1, 1);

    for (int it=0; it<nk; it++){
        if (it+2 < nk) issue(it+2, (it+2)%3);
        if (it+1 < nk) cp_wait<1>(); else cp_wait<0>();
        __syncthreads();

        const uint32_t* As = (const uint32_t*)(dynsm + (it%3)*TG_STAGE);
        const uint32_t* Bs = (const uint32_t*)(dynsm + (it%3)*TG_STAGE + TG_ABUF);

        #pragma unroll
        for (int ks=0; ks<4; ks++){
            uint32_t af[2][4];
            #pragma unroll
            for (int mt=0; mt<2; mt++){
                int r = wm*32 + mt*16 + gid;
                af[mt][0] = As[r*36 + ks*8 + tig];
                af[mt][1] = As[(r+8)*36 + ks*8 + tig];
                af[mt][2] = As[r*36 + ks*8 + tig + 4];
                af[mt][3] = As[(r+8)*36 + ks*8 + tig + 4];
            }
            uint32_t bf[8][2];
            #pragma unroll
            for (int nt=0; nt<8; nt++){
                int n = wn*64 + nt*8 + gid;
                bf[nt][0] = Bs[(ks*8 + tig)*132 + n];
                bf[nt][1] = Bs[(ks*8 + tig + 4)*132 + n];
            }
            #pragma unroll
            for (int mt=0; mt<2; mt++)
                #pragma unroll
                for (int nt=0; nt<8; nt++)
                    mma_tf32(acc[mt][nt], af[mt], bf[nt]);
        }
        __syncthreads();
    }

    if (EPI == 2){
        #pragma unroll
        for (int mt=0; mt<2; mt++){
            int row0 = rowb + wm*32 + mt*16 + gid;
            float s0 = 0.f, s1 = 0.f;
            #pragma unroll
            for (int nt=0; nt<8; nt++){
                int col = colb + wn*64 + nt*8 + 2*tig;
                float b0 = bias[col], b1 = bias[col+1];
                float u0 = us[col],  u1 = us[col+1];
                float2 x0 = *(const float2*)&xadd[(size_t)row0*HH + col];
                float2 x1 = *(const float2*)&xadd[(size_t)(row0+8)*HH + col];
                float v;
                v = acc[mt][nt][0] + b0 + x0.x; s0 += (v>0.f? v:0.f)*u0;
                v = acc[mt][nt][1] + b1 + x0.y; s0 += (v>0.f? v:0.f)*u1;
                v = acc[mt][nt][2] + b0 + x1.x; s1 += (v>0.f? v:0.f)*u0;
                v = acc[mt][nt][3] + b1 + x1.y; s1 += (v>0.f? v:0.f)*u1;
            }
            s0 += __shfl_xor_sync(0xffffffffu, s0, 1);
            s0 += __shfl_xor_sync(0xffffffffu, s0, 2);
            s1 += __shfl_xor_sync(0xffffffffu, s1, 1);
            s1 += __shfl_xor_sync(0xffffffffu, s1, 2);
            if (tig == 0){
                atomicAdd(&g_score[row0], s0);
                atomicAdd(&g_score[row0+8], s1);
            }
        }
    } else {
        #pragma unroll
        for (int mt=0; mt<2; mt++){
            #pragma unroll
            for (int nt=0; nt<8; nt++){
                int col = colb + wn*64 + nt*8 + 2*tig;
                int row = rowb + wm*32 + mt*16 + gid;
                #pragma unroll
                for (int i=0; i<4; i++){
                    int cc = col + (i & 1);
                    int rr = row + ((i >> 1) ? 8 : 0);
                    if (!NG || cc < N){
                        float v = acc[mt][nt][i];
                        if (EPI != 3) v += bias[cc];
                        if (EPI == 1) v = v > 0.f ? v : 0.f;
                        C[(size_t)rr*ldc + cc] = v;
                    }
                }
            }
        }
    }
}

// ---------------- persistent scan kernel (round-10 form, unchanged) ----------------
__device__ __forceinline__ void gsync(int& epoch)
{
    __syncthreads();
    if (threadIdx.x == 0){
        __threadfence();
        atomicAdd(&g_bar, 1u);
        unsigned tgt = (unsigned)epoch * NBLK;
        while (*((volatile unsigned*)&g_bar) < tgt) { }
    }
    epoch++;
    __syncthreads();
}

__global__ void __launch_bounds__(256, 1)
k_scan(const int* __restrict__ nei_h,
       const float* __restrict__ Wzh,
       const float* __restrict__ Whh,
       const float* __restrict__ Ur)
{
    extern __shared__ float smem[];
    float* Wz_s = smem;
    float* Wh_s = Wz_s + 512*32;
    float* ringf = Wh_s + 512*32;

    const int tid = threadIdx.x;
    const int blk = blockIdx.x;
    const int rt = blk >> 4, ct = blk & 15;
    const int r0 = rt*64, c0 = ct*32;
    const int warp = tid >> 5, lane = tid & 31;
    const int wm = warp & 3, wn = warp >> 2;
    const int gid = lane >> 2, tig = lane & 3;
    const int id4a = tid*2, id4b = tid*2+1;
    const int sra = id4a >> 3, ska = (id4a & 7)*4;
    const int srb = id4b >> 3, skb = (id4b & 7)*4;
    const int ur_r = tid >> 3, ur_c = (tid & 7)*4;

    const uint32_t ring_u = (uint32_t)__cvta_generic_to_shared(ringf);

    for (int idx = tid; idx < 512*32; idx += 256){
        int k = idx >> 5; int cc = idx & 31;
        int sw = cc ^ ((k & 3) << 3);
        Wz_s[k*32 + sw] = Wzh[(size_t)k*HH + c0 + cc];
        Wh_s[k*32 + sw] = Whh[(size_t)k*HH + c0 + cc];
    }
    __syncthreads();

    const uint32_t* Wz32 = (const uint32_t*)Wz_s;
    const uint32_t* Wh32 = (const uint32_t*)Wh_s;

    int epoch = 1;

    for (int t = 0; t < TT; t++){
        // ---- phase A ----
        #pragma unroll
        for (int rb=0; rb<4; rb++){
            int b = blk*4 + rb;
            const int* idx = nei_h + ((size_t)b*TT + t)*MAX_NB;
            int ii[8];
            #pragma unroll
            for (int n=0;n<8;n++) ii[n] = idx[n];
            #pragma unroll
            for (int cc=0; cc<2; cc++){
                int ch = tid + cc*256;
                float xr = g_Xr[((size_t)b*TT + t)*HH + ch];
                float ah=0.f, ag=0.f;
                #pragma unroll
                for (int n=0;n<8;n++){
                    size_t base = (size_t)ii[n]*HH + ch;
                    float hv = __ldcg(&g_table[base]);
                    float uv = __ldcg(&g_tableU[base]);
                    ah += hv;
                    ag += hv * sigf(xr + uv);
                }
                g_sumh[b*HH+ch] = ah;
                g_sumg[b*HH+ch] = ag;
            }
        }
        gsync(epoch);

        // ---- phase B ----
        {
            float accz[2][4], acch[2][4];
            #pragma unroll
            for (int nt=0;nt<2;nt++)
                #pragma unroll
                for (int i=0;i<4;i++){ accz[nt][i]=0.f; acch[nt][i]=0.f; }

            auto issueB = [&](int chk){
                uint32_t sa = ring_u + (chk & 3)*RING_STAGE_B;
                cp_async16(sa + (sra*36+ska)*4, &g_sumh[(size_t)(r0+sra)*HH + chk*32 + ska]);
                cp_async16(sa + (srb*36+skb)*4, &g_sumh[(size_t)(r0+srb)*HH + chk*32 + skb]);
                cp_async16(sa + 9216 + (sra*36+ska)*4, &g_sumg[(size_t)(r0+sra)*HH + chk*32 + ska]);
                cp_async16(sa + 9216 + (srb*36+skb)*4, &g_sumg[(size_t)(r0+srb)*HH + chk*32 + skb]);
                cp_commit();
            };
            issueB(0); issueB(1); issueB(2);

            for (int chk=0; chk<16; chk++){
                if (chk < 14) cp_wait<2>(); else if (chk == 14) cp_wait<1>(); else cp_wait<0>();
                __syncthreads();
                if (chk+3 < 16) issueB(chk+3);

                const uint32_t* Ah = (const uint32_t*)(ringf + (chk & 3)*4608);
                const uint32_t* Ag = Ah + 2304;

                #pragma unroll
                for (int ks=0; ks<4; ks++){
                    int rb0 = wm*16 + gid;
                    uint32_t ah[4], ag[4];
                    ah[0]=Ah[rb0*36 + ks*8 + tig];     ah[1]=Ah[(rb0+8)*36 + ks*8 + tig];
                    ah[2]=Ah[rb0*36 + ks*8 + tig + 4]; ah[3]=Ah[(rb0+8)*36 + ks*8 + tig + 4];
                    ag[0]=Ag[rb0*36 + ks*8 + tig];     ag[1]=Ag[(rb0+8)*36 + ks*8 + tig];
                    ag[2]=Ag[rb0*36 + ks*8 + tig + 4]; ag[3]=Ag[(rb0+8)*36 + ks*8 + tig + 4];
                    int kg = chk*32 + ks*8;
                    #pragma unroll
                    for (int nt=0; nt<2; nt++){
                        int n = wn*16 + nt*8 + gid;
                        int nsw = n ^ (tig << 3);
                        uint32_t bz[2], bh[2];
                        bz[0] = Wz32[(kg+tig)*32 + nsw];
                        bz[1] = Wz32[(kg+tig+4)*32 + nsw];
                        bh[0] = Wh32[(kg+tig)*32 + nsw];
                        bh[1] = Wh32[(kg+tig+4)*32 + nsw];
                        mma_tf32(accz[nt], ah, bz);
                        mma_tf32(acch[nt], ag, bh);
                    }
                }
            }

            #pragma unroll
            for (int nt=0; nt<2; nt++){
                #pragma unroll
                for (int half=0; half<2; half++){
                    int b   = r0 + wm*16 + gid + half*8;
                    int col = c0 + wn*16 + nt*8 + tig*2;
                    size_t xi = ((size_t)b*TT + t)*HH + col;
                    float2 xz = *(const float2*)&g_Xz[xi];
                    float2 xh = *(const float2*)&g_Xh[xi];
                    float2 sh = __ldcg((const float2*)&g_sumh[(size_t)b*HH + col]);
                    float z0 = sigf(xz.x + accz[nt][half*2+0]);
                    float z1 = sigf(xz.y + accz[nt][half*2+1]);
                    float p0 = tanhf(xh.x + acch[nt][half*2+0]);
                    float p1 = tanhf(xh.y + acch[nt][half*2+1]);
                    float2 out;
                    out.x = (1.f - z0)*sh.x + z0*p0;
                    out.y = (1.f - z1)*sh.y + z1*p1;
                    *(float2*)&g_table[((size_t)b*TT + t + 1)*HH + col] = out;
                }
            }
        }
        gsync(epoch);

        if (t == TT-1) break;

        // ---- phase C ----
        {
            float accu[2][4];
            #pragma unroll
            for (int nt=0;nt<2;nt++)
                #pragma unroll
                for (int i=0;i<4;i++) accu[nt][i]=0.f;

            auto issueC = [&](int chk){
                uint32_t sa = ring_u + (chk & 3)*RING_STAGE_B;
                cp_async16(sa + (sra*36+ska)*4, &g_table[((size_t)(r0+sra)*TT + t + 1)*HH + chk*32 + ska]);
                cp_async16(sa + (srb*36+skb)*4, &g_table[((size_t)(r0+srb)*TT + t + 1)*HH + chk*32 + skb]);
                cp_async16(sa + 9216 + (ur_r*40 + ur_c)*4, &Ur[(size_t)(chk*32 + ur_r)*HH + c0 + ur_c]);
                cp_commit();
            };
            issueC(0); issueC(1); issueC(2);

            for (int chk=0; chk<16; chk++){
                if (chk < 14) cp_wait<2>(); else if (chk == 14) cp_wait<1>(); else cp_wait<0>();
                __syncthreads();
                if (chk+3 < 16) issueC(chk+3);

                const uint32_t* Ah = (const uint32_t*)(ringf + (chk & 3)*4608);
                const uint32_t* Uc = Ah + 2304;

                #pragma unroll
                for (int ks=0; ks<4; ks++){
                    int rb0 = wm*16 + gid;
                    uint32_t ah[4];
                    ah[0]=Ah[rb0*36 + ks*8 + tig];     ah[1]=Ah[(rb0+8)*36 + ks*8 + tig];
                    ah[2]=Ah[rb0*36 + ks*8 + tig + 4]; ah[3]=Ah[(rb0+8)*36 + ks*8 + tig + 4];
                    #pragma unroll
                    for (int nt=0; nt<2; nt++){
                        int n = wn*16 + nt*8 + gid;
                        uint32_t bu[2];
                        bu[0] = Uc[(ks*8 + tig)*40 + n];
                        bu[1] = Uc[(ks*8 + tig + 4)*40 + n];
                        mma_tf32(accu[nt], ah, bu);
                    }
                }
            }

            #pragma unroll
            for (int nt=0; nt<2; nt++){
                #pragma unroll
                for (int half=0; half<2; half++){
                    int b   = r0 + wm*16 + gid + half*8;
                    int col = c0 + wn*16 + nt*8 + tig*2;
                    float2 out;
                    out.x = accu[nt][half*2+0];
                    out.y = accu[nt][half*2+1];
                    *(float2*)&g_tableU[((size_t)b*TT + t + 1)*HH + col] = out;
                }
            }
        }
        gsync(epoch);
    }
}

// ---------------- deferred o gather (o-half only) ----------------
__global__ void k_oall(const int* __restrict__ nei_o, const int* __restrict__ root_nei)
{
    int i = blockIdx.x;
    int c = blockIdx.y*256 + threadIdx.x;
    if (i < BT) {
        int tt = i % TT;
        const int* idx = nei_o + (size_t)i*MAX_NB;
        float o = 0.f;
        #pragma unroll
        for (int n=0;n<MAX_NB;n++){
            int id = idx[n];
            if (id > 0 && ((id-1) % TT) < tt) o += g_table[(size_t)id*HH + c];
        }
        g_stopO[(size_t)i*HH + c] = o;
    } else {
        int b = i - BT;
        const int* idx = root_nei + (size_t)b*MAX_NB;
        float o = 0.f;
        #pragma unroll
        for (int n=0;n<MAX_NB;n++) o += g_table[(size_t)idx[n]*HH + c];
        g_stopO[(size_t)i*HH + c] = o;
    }
}

// ---------------- stop loss / acc ----------------
__global__ void k_stoploss(const int* __restrict__ direction, const float* __restrict__ usb)
{
    int i = blockIdx.x*256 + threadIdx.x;
    float li = 0.f, ci = 0.f;
    if (i < NSTOP){
        float s = g_score[i] + usb[0];
        float tgt = (i < BT) ? (float)direction[i] : 0.f;
        float sp = (s > 0.f) ? (s + log1pf(expf(-s))) : log1pf(expf(s));
        li = sp - s*tgt;
        float pred = (s >= 0.f) ? 1.f : 0.f;
        ci = (pred == tgt) ? 1.f : 0.f;
    }
    __shared__ float rl[256], rc[256];
    rl[threadIdx.x]=li; rc[threadIdx.x]=ci;
    __syncthreads();
    for (int st=128; st>0; st>>=1){
        if (threadIdx.x < st){ rl[threadIdx.x]+=rl[threadIdx.x+st]; rc[threadIdx.x]+=rc[threadIdx.x+st]; }
        __syncthreads();
    }
    if (threadIdx.x==0){
        atomicAdd(&g_red[3], rl[0]);
        atomicAdd(&g_red[4], rc[0]);
    }
}

// ---------------- pred head CE / acc over compacted rows ----------------
__global__ void k_ce(const int* __restrict__ target)
{
    int slot = blockIdx.x;
    if (slot >= g_cnt) return;
    int i = g_list[slot];
    int t = threadIdx.x;
    const float* S = g_predS + (size_t)slot*VV;
    float val[4];
    float lmax = -1e30f; int lidx = 0;
    #pragma unroll
    for (int r=0;r<4;r++){
        int v = t + 256*r;
        if (v < VV){
            float x = S[v];
            val[r] = x;
            if (x > lmax){ lmax = x; lidx = v; }
        } else val[r] = -1e30f;
    }
    __shared__ float smax[256]; __shared__ int sidx[256];
    smax[t]=lmax; sidx[t]=lidx;
    __syncthreads();
    for (int st=128; st>0; st>>=1){
        if (t < st){
            float o = smax[t+st]; int oi = sidx[t+st];
            if (o > smax[t] || (o == smax[t] && oi < sidx[t])){ smax[t]=o; sidx[t]=oi; }
        }
        __syncthreads();
    }
    float m = smax[0]; int am = sidx[0];
    __syncthreads();
    float se = 0.f;
    #pragma unroll
    for (int r=0;r<4;r++){
        int v = t + 256*r;
        if (v < VV) se += expf(val[r] - m);
    }
    __shared__ float ssum[256];
    ssum[t]=se;
    __syncthreads();
    for (int st=128; st>0; st>>=1){
        if (t < st) ssum[t]+=ssum[t+st];
        __syncthreads();
    }
    if (t==0){
        float lse = m + logf(ssum[0]);
        int tg = target[i];
        float ce = lse - S[tg];
        atomicAdd(&g_red[0], ce);
        atomicAdd(&g_red[1], (am==tg) ? 1.f : 0.f);
        atomicAdd(&g_red[2], 1.f);
    }
}

__global__ void k_final(float* out)
{
    out[0] = g_red[0] / (float)BB;
    out[1] = g_red[3] / (float)BB;
    out[2] = g_red[1] / g_red[2];
    out[3] = g_red[4] / (float)NSTOP;
}

// ---------------- host launch ----------------
extern "C" void kernel_launch(void* const* d_in, const int* in_sizes, int n_in,
                              void* d_out, int out_size)
{
    const float* node_rep = (const float*)d_in[0];
    const int*   clique   = (const int*)  d_in[1];
    const int*   rclique  = (const int*)  d_in[2];
    const int*   nei_h    = (const int*)  d_in[3];
    const int*   nei_o    = (const int*)  d_in[4];
    const int*   rnei     = (const int*)  d_in[5];
    const int*   dir      = (const int*)  d_in[6];
    const int*   ptgt     = (const int*)  d_in[7];
    const float* Wz  = (const float*)d_in[8];
    const float* Wzb = (const float*)d_in[9];
    const float* Wr  = (const float*)d_in[10];
    const float* Wrb = (const float*)d_in[11];
    const float* Ur  = (const float*)d_in[12];
    const float* Wh  = (const float*)d_in[13];
    const float* Whb = (const float*)d_in[14];
    const float* Ww  = (const float*)d_in[15];
    const float* Wwb = (const float*)d_in[16];
    const float* Uw  = (const float*)d_in[17];
    const float* Ub  = (const float*)d_in[18];
    const float* Wo  = (const float*)d_in[19];
    const float* Wob = (const float*)d_in[20];
    const float* Us  = (const float*)d_in[21];
    const float* Usb = (const float*)d_in[22];

    float *tb, *tbU, *nZ, *nR, *nH, *nS, *stopO, *predH, *predS, *score, *red;
    unsigned* bar; int* cnt; int* list;
    cudaGetSymbolAddress((void**)&tb,    g_table);
    cudaGetSymbolAddress((void**)&tbU,   g_tableU);
    cudaGetSymbolAddress((void**)&nZ,    g_nodeZ);
    cudaGetSymbolAddress((void**)&nR,    g_nodeR);
    cudaGetSymbolAddress((void**)&nH,    g_nodeH);
    cudaGetSymbolAddress((void**)&nS,    g_nodeS);
    cudaGetSymbolAddress((void**)&stopO, g_stopO);
    cudaGetSymbolAddress((void**)&predH, g_predH);
    cudaGetSymbolAddress((void**)&predS, g_predS);
    cudaGetSymbolAddress((void**)&score, g_score);
    cudaGetSymbolAddress((void**)&red,   g_red);
    cudaGetSymbolAddress((void**)&bar,   g_bar);
    cudaGetSymbolAddress((void**)&cnt,   g_cnt);
    cudaGetSymbolAddress((void**)&list,  g_list);

    static int attr_set = 0;
    if (!attr_set){
        cudaFuncSetAttribute(k_scan, cudaFuncAttributeMaxDynamicSharedMemorySize, SMEM_SCAN);
        cudaFuncSetAttribute(tgemm<3,false,true,0>,  cudaFuncAttributeMaxDynamicSharedMemorySize, SMEM_TG);
        cudaFuncSetAttribute(tgemm<2,false,false,0>, cudaFuncAttributeMaxDynamicSharedMemorySize, SMEM_TG);
        cudaFuncSetAttribute(tgemm<1,false,false,1>, cudaFuncAttributeMaxDynamicSharedMemorySize, SMEM_TG);
        cudaFuncSetAttribute(tgemm<0,true,false,2>,  cudaFuncAttributeMaxDynamicSharedMemorySize, SMEM_TG);
        attr_set = 1;
    }

    cudaMemsetAsync(tb,   0, sizeof(float)*(size_t)NMSG*HH);
    cudaMemsetAsync(tbU,  0, sizeof(float)*(size_t)NMSG*HH);
    cudaMemsetAsync(score,0, sizeof(float)*NSTOP);
    cudaMemsetAsync(red,  0, sizeof(float)*8);
    cudaMemsetAsync(bar,  0, sizeof(unsigned));
    cudaMemsetAsync(cnt,  0, sizeof(int));
    cudaMemsetAsync(list, 0, sizeof(int)*BT);

    // node-level projections (Wz_x, Wr, Wh_x, Uw_x) in one launch
    dim3 gN(4, (BB*N_AT)/128, 4);
    tgemm<3,false,true,0><<<gN, 256, SMEM_TG>>>(node_rep, HH, Wz, HH, nullptr, nZ, HH,
                                                HH, HH, nullptr, nullptr,
                                                Wr, Wh, Uw, nR, nH, nS);
    k_xproj<<<BT, 256>>>(clique, Wzb, Wrb, Whb);
    k_rootS<<<BB, 256>>>(rclique);
    k_compact<<<BT/256, 256>>>(dir);

    // sequential scan
    const float* Wzh = Wz + (size_t)HH*HH;
    const float* Whh = Wh + (size_t)HH*HH;
    k_scan<<<NBLK, 256, SMEM_SCAN>>>(nei_h, Wzh, Whh, Ur);

    // stop head: o@Uw_o with x@Uw_x added in epilogue
    k_oall<<<dim3(NSTOP,2), 256>>>(nei_o, rnei);
    float* stopX; cudaGetSymbolAddress((void**)&stopX, g_stopX);
    tgemm<2,false,false,0><<<dim3(4, NSTOP/128), 256, SMEM_TG>>>(stopO, HH,
        Uw + (size_t)HH*HH, HH, Ub, nullptr, 0, HH, HH, Us, stopX,
        nullptr, nullptr, nullptr, nullptr, nullptr, nullptr);
    k_stoploss<<<NSTOP/256, 256>>>(dir, Usb);

    // pred head over compacted rows (direction==1)
    tgemm<1,false,false,1><<<dim3(4, BT/128), 256, SMEM_TG>>>(tb + HH, HH, Ww, HH, Wwb,
        predH, HH, HH, HH, nullptr, nullptr,
        nullptr, nullptr, nullptr, nullptr, nullptr, nullptr);
    tgemm<0,true,false,2><<<dim3(7, BT/128), 256, SMEM_TG>>>(predH, HH, Wo, VV, Wob,
        predS, VV, VV, HH, nullptr, nullptr,
        nullptr, nullptr, nullptr, nullptr, nullptr, nullptr);
    k_ce<<<BT, 256>>>(ptgt);

    k_final<<<1,1>>>((float*)d_out);
}

// round 14
// speedup vs baseline: 1.4839x; 1.2466x over previous
#include <cuda_runtime.h>
#include <cuda_bf16.h>
#include <math.h>
#include <stdint.h>

#define BB 512
#define TT 64
#define HH 512
#define VV 780
#define N_AT 40
#define KC 4
#define MAX_NB 8
#define NMSG (BB*TT+1)
#define BT (BB*TT)
#define NSTOP (BT+BB)
#define H2 (2*HH)
#define NBLK 128
#define PW 1024   // pair row width: [h(512) | Uh(512)]

// k_scan smem: packed weight fragments (128KB) + 4-stage ring (72KB)
#define WF_FLOATS (16*4*2*2*32*4)     // 32768 floats = 128KB
#define RING_STAGE_B 18432
#define SMEM_SCAN (WF_FLOATS*4 + 4*RING_STAGE_B)   // 204800 B

// tgemm: 3-stage ring of (A[128][36] + B[32][132]) fp32 tiles
#define TG_ABUF (128*36)
#define TG_BBUF (32*132)
#define TG_STAGE (TG_ABUF + TG_BBUF)
#define SMEM_TG (3*TG_STAGE*4)

// ---------------- device scratch ----------------
// g_pair row m (b-major, m = b*TT+t+1; row 0 = zero): [h | U_r·h]
__device__ float g_pair  [(size_t)NMSG*PW];
__device__ float g_nodeZ [BB*N_AT*HH];
__device__ float g_nodeR [BB*N_AT*HH];
__device__ float g_nodeH [BB*N_AT*HH];
__device__ float g_nodeS [BB*N_AT*HH];
__device__ float g_Xz    [BT*HH];
__device__ float g_Xr    [BT*HH];
__device__ float g_Xh    [BT*HH];
__device__ float g_sumh  [BB*HH];
__device__ float g_sumg  [BB*HH];
__device__ float g_stopO [NSTOP*HH];
__device__ float g_stopX [NSTOP*HH];
__device__ float g_predH [BT*HH];
__device__ float g_predS [BT*VV];
__device__ float g_score [NSTOP];
__device__ float g_red   [8];
__device__ unsigned g_bar;
__device__ int g_cnt;
__device__ int g_list[BT];

__device__ __forceinline__ float sigf(float x){ return 1.f/(1.f+expf(-x)); }

__device__ __forceinline__ void cp_async16(uint32_t dst, const void* src){
    asm volatile("cp.async.cg.shared.global [%0], [%1], 16;\n" :: "r"(dst), "l"(src));
}
__device__ __forceinline__ void cp_async16z(uint32_t dst, const void* src, int bytes){
    asm volatile("cp.async.cg.shared.global [%0], [%1], 16, %2;\n" :: "r"(dst), "l"(src), "r"(bytes));
}
__device__ __forceinline__ void cp_commit(){ asm volatile("cp.async.commit_group;\n"); }
template<int N> __device__ __forceinline__ void cp_wait(){ asm volatile("cp.async.wait_group %0;\n" :: "n"(N)); }

__device__ __forceinline__ void mma_tf32(float* d, const uint32_t* a, const uint32_t* b){
    asm volatile(
        "mma.sync.aligned.m16n8k8.row.col.f32.tf32.tf32.f32 "
        "{%0,%1,%2,%3},{%4,%5,%6,%7},{%8,%9},{%0,%1,%2,%3};\n"
        : "+f"(d[0]), "+f"(d[1]), "+f"(d[2]), "+f"(d[3])
        : "r"(a[0]), "r"(a[1]), "r"(a[2]), "r"(a[3]), "r"(b[0]), "r"(b[1]));
}

// ---------------- gather node projections into per-(b,t) arrays ----------------
__global__ void k_xproj(const int* __restrict__ cidx,
                        const float* __restrict__ bz,
                        const float* __restrict__ br,
                        const float* __restrict__ bh)
{
    int i = blockIdx.x;
    int b = i / TT;
    const int* ci = cidx + (size_t)i*KC;
    int r0 = b*N_AT;
    #pragma unroll
    for (int cc=0; cc<2; cc++){
        int c = threadIdx.x + cc*256;
        float sz = bz[c], sr = br[c], sh = bh[c], ss = 0.f;
        #pragma unroll
        for (int k=0;k<KC;k++){
            size_t row = (size_t)(r0 + ci[k])*HH + c;
            sz += g_nodeZ[row];
            sr += g_nodeR[row];
            sh += g_nodeH[row];
            ss += g_nodeS[row];
        }
        g_Xz[(size_t)i*HH + c] = sz;
        g_Xr[(size_t)i*HH + c] = sr;
        g_Xh[(size_t)i*HH + c] = sh;
        g_stopX[(size_t)i*HH + c] = ss;
    }
}

__global__ void k_rootS(const int* __restrict__ rcidx)
{
    int b = blockIdx.x;
    const int* ci = rcidx + (size_t)b*KC;
    #pragma unroll
    for (int cc=0; cc<2; cc++){
        int c = threadIdx.x + cc*256;
        float ss = 0.f;
        #pragma unroll
        for (int k=0;k<KC;k++)
            ss += g_nodeS[(size_t)(b*N_AT + ci[k])*HH + c];
        g_stopX[(size_t)(BT + b)*HH + c] = ss;
    }
}

__global__ void k_compact(const int* __restrict__ direction)
{
    int i = blockIdx.x*256 + threadIdx.x;
    if (i < BT && direction[i] == 1){
        int s = atomicAdd(&g_cnt, 1);
        g_list[s] = i;
    }
}

// ---------------- tf32 tensor-core GEMM ----------------
template<int EPI, bool NG, bool ZSEL, int GMODE>
__global__ void __launch_bounds__(256)
tgemm(const float* __restrict__ A, int lda,
      const float* __restrict__ Bm0, int ldb,
      const float* __restrict__ bias,
      float* __restrict__ C0, int ldc,
      int N, int K,
      const float* __restrict__ us,
      const float* __restrict__ xadd,
      const float* Bm1, const float* Bm2, const float* Bm3,
      float* C1, float* C2, float* C3)
{
    extern __shared__ float dynsm[];
    const int by = blockIdx.y, bx = blockIdx.x;
    const int rowb = by*128, colb = bx*128;
    if (GMODE){ if (rowb >= g_cnt) return; }

    const int tid  = threadIdx.x;
    const int warp = tid >> 5, lane = tid & 31;
    const int wm = warp & 3, wn = warp >> 2;
    const int gid = lane >> 2, tig = lane & 3;

    const float* Bm = Bm0;
    float* C = C0;
    if (ZSEL){
        if (blockIdx.z == 1){ Bm = Bm1; C = C1; }
        else if (blockIdx.z == 2){ Bm = Bm2; C = C2; }
        else if (blockIdx.z == 3){ Bm = Bm3; C = C3; }
    }

    uint32_t smem_base = (uint32_t)__cvta_generic_to_shared(dynsm);

    float acc[2][8][4];
    #pragma unroll
    for (int mt=0;mt<2;mt++)
        #pragma unroll
        for (int nt=0;nt<8;nt++)
            #pragma unroll
            for (int i=0;i<4;i++) acc[mt][nt][i]=0.f;

    const int nk = K >> 5;

    auto issue = [&](int kt, int stage){
        uint32_t sa = smem_base + stage*TG_STAGE*4;
        uint32_t sb = sa + TG_ABUF*4;
        #pragma unroll
        for (int i=0;i<4;i++){
            int q = tid + 256*i;
            int r = q >> 3, k4 = (q & 7)*4;
            size_t arow = (GMODE == 1) ? (size_t)g_list[rowb + r] : (size_t)(rowb + r);
            cp_async16(sa + (r*36 + k4)*4, A + arow*lda + kt*32 + k4);
        }
        #pragma unroll
        for (int i=0;i<4;i++){
            int q = tid + 256*i;
            int kr = q >> 5, n4 = (q & 31)*4;
            uint32_t dst = sb + (kr*132 + n4)*4;
            if (NG){
                int col = colb + n4;
                int bytes = (col + 3 < N) ? 16 : ((col < N) ? (N - col)*4 : 0);
                const float* src = Bm + (size_t)(kt*32 + kr)*ldb + (bytes ? col : 0);
                cp_async16z(dst, src, bytes);
            } else {
                cp_async16(dst, Bm + (size_t)(kt*32 + kr)*ldb + colb + n4);
            }
        }
        cp_commit();
    };

    issue(0, 0);
    if (nk > 1) issue(1, 1);

    for (int it=0; it<nk; it++){
        if (it+2 < nk) issue(it+2, (it+2)%3);
        if (it+1 < nk) cp_wait<1>(); else cp_wait<0>();
        __syncthreads();

        const uint32_t* As = (const uint32_t*)(dynsm + (it%3)*TG_STAGE);
        const uint32_t* Bs = (const uint32_t*)(dynsm + (it%3)*TG_STAGE + TG_ABUF);

        #pragma unroll
        for (int ks=0; ks<4; ks++){
            uint32_t af[2][4];
            #pragma unroll
            for (int mt=0; mt<2; mt++){
                int r = wm*32 + mt*16 + gid;
                af[mt][0] = As[r*36 + ks*8 + tig];
                af[mt][1] = As[(r+8)*36 + ks*8 + tig];
                af[mt][2] = As[r*36 + ks*8 + tig + 4];
                af[mt][3] = As[(r+8)*36 + ks*8 + tig + 4];
            }
            uint32_t bf[8][2];
            #pragma unroll
            for (int nt=0; nt<8; nt++){
                int n = wn*64 + nt*8 + gid;
                bf[nt][0] = Bs[(ks*8 + tig)*132 + n];
                bf[nt][1] = Bs[(ks*8 + tig + 4)*132 + n];
            }
            #pragma unroll
            for (int mt=0; mt<2; mt++)
                #pragma unroll
                for (int nt=0; nt<8; nt++)
                    mma_tf32(acc[mt][nt], af[mt], bf[nt]);
        }
        __syncthreads();
    }

    if (EPI == 2){
        #pragma unroll
        for (int mt=0; mt<2; mt++){
            int row0 = rowb + wm*32 + mt*16 + gid;
            float s0 = 0.f, s1 = 0.f;
            #pragma unroll
            for (int nt=0; nt<8; nt++){
                int col = colb + wn*64 + nt*8 + 2*tig;
                float b0 = bias[col], b1 = bias[col+1];
                float u0 = us[col],  u1 = us[col+1];
                float2 x0 = *(const float2*)&xadd[(size_t)row0*HH + col];
                float2 x1 = *(const float2*)&xadd[(size_t)(row0+8)*HH + col];
                float v;
                v = acc[mt][nt][0] + b0 + x0.x; s0 += (v>0.f? v:0.f)*u0;
                v = acc[mt][nt][1] + b1 + x0.y; s0 += (v>0.f? v:0.f)*u1;
                v = acc[mt][nt][2] + b0 + x1.x; s1 += (v>0.f? v:0.f)*u0;
                v = acc[mt][nt][3] + b1 + x1.y; s1 += (v>0.f? v:0.f)*u1;
            }
            s0 += __shfl_xor_sync(0xffffffffu, s0, 1);
            s0 += __shfl_xor_sync(0xffffffffu, s0, 2);
            s1 += __shfl_xor_sync(0xffffffffu, s1, 1);
            s1 += __shfl_xor_sync(0xffffffffu, s1, 2);
            if (tig == 0){
                atomicAdd(&g_score[row0], s0);
                atomicAdd(&g_score[row0+8], s1);
            }
        }
    } else {
        #pragma unroll
        for (int mt=0; mt<2; mt++){
            #pragma unroll
            for (int nt=0; nt<8; nt++){
                int col = colb + wn*64 + nt*8 + 2*tig;
                int row = rowb + wm*32 + mt*16 + gid;
                #pragma unroll
                for (int i=0; i<4; i++){
                    int cc = col + (i & 1);
                    int rr = row + ((i >> 1) ? 8 : 0);
                    if (!NG || cc < N){
                        float v = acc[mt][nt][i];
                        if (EPI != 3) v += bias[cc];
                        if (EPI == 1) v = v > 0.f ? v : 0.f;
                        C[(size_t)rr*ldc + cc] = v;
                    }
                }
            }
        }
    }
}

// ---------------- persistent scan kernel ----------------
__device__ __forceinline__ void gsync(int& epoch)
{
    __syncthreads();
    if (threadIdx.x == 0){
        __threadfence();
        atomicAdd(&g_bar, 1u);
        unsigned tgt = (unsigned)epoch * NBLK;
        while (*((volatile unsigned*)&g_bar) < tgt) { }
    }
    epoch++;
    __syncthreads();
}

__global__ void __launch_bounds__(256, 1)
k_scan(const int* __restrict__ nei_h,
       const float* __restrict__ Wzh,
       const float* __restrict__ Whh,
       const float* __restrict__ Ur)
{
    extern __shared__ float smem[];
    float4* WF  = (float4*)smem;               // packed Wz/Wh fragments (128KB)
    float* ringf = smem + WF_FLOATS;           // 4 stages x 4608 floats

    const int tid = threadIdx.x;
    const int blk = blockIdx.x;
    const int rt = blk >> 4, ct = blk & 15;
    const int r0 = rt*64, c0 = ct*32;
    const int warp = tid >> 5, lane = tid & 31;
    const int wm = warp & 3, wn = warp >> 2;
    const int gid = lane >> 2, tig = lane & 3;
    const int id4a = tid*2, id4b = tid*2+1;
    const int sra = id4a >> 3, ska = (id4a & 7)*4;
    const int srb = id4b >> 3, skb = (id4b & 7)*4;
    const int ur_r = tid >> 3, ur_c = (tid & 7)*4;

    const uint32_t ring_u = (uint32_t)__cvta_generic_to_shared(ringf);

    // stage Wz/Wh in fragment-packed order: group g = ((chunk*4+ks)*2+wns)*2+nt
    for (int g = warp; g < 256; g += 8){
        int nt  = g & 1, wns = (g >> 1) & 1, ks = (g >> 2) & 3, chunk = g >> 4;
        int krow = chunk*32 + ks*8 + tig;
        int col  = c0 + wns*16 + nt*8 + gid;
        float4 v;
        v.x = Wzh[(size_t)krow*HH + col];
        v.y = Wzh[(size_t)(krow+4)*HH + col];
        v.z = Whh[(size_t)krow*HH + col];
        v.w = Whh[(size_t)(krow+4)*HH + col];
        WF[g*32 + lane] = v;
    }
    __syncthreads();

    int epoch = 1;

    for (int t = 0; t < TT; t++){
        // ---- phase A: gather sum_h, sum_g (float2, pair rows) ----
        {
            const int ch2 = tid*2;
            #pragma unroll
            for (int rb=0; rb<4; rb++){
                int b = blk*4 + rb;
                const int* idx = nei_h + ((size_t)b*TT + t)*MAX_NB;
                const float* pr[8];
                #pragma unroll
                for (int n=0;n<8;n++) pr[n] = g_pair + (size_t)idx[n]*PW;
                float2 xr = *(const float2*)&g_Xr[((size_t)b*TT + t)*HH + ch2];
                float2 ah = make_float2(0.f,0.f), ag = make_float2(0.f,0.f);
                #pragma unroll
                for (int n=0;n<8;n++){
                    float2 hv = __ldcg((const float2*)(pr[n] + ch2));
                    float2 uv = __ldcg((const float2*)(pr[n] + 512 + ch2));
                    ah.x += hv.x; ah.y += hv.y;
                    ag.x += hv.x * sigf(xr.x + uv.x);
                    ag.y += hv.y * sigf(xr.y + uv.y);
                }
                *(float2*)&g_sumh[b*HH+ch2] = ah;
                *(float2*)&g_sumg[b*HH+ch2] = ag;
            }
        }
        gsync(epoch);

        // ---- phase B: dual tf32 GEMM + GRU epilogue ----
        {
            float accz[2][4], acch[2][4];
            #pragma unroll
            for (int nt=0;nt<2;nt++)
                #pragma unroll
                for (int i=0;i<4;i++){ accz[nt][i]=0.f; acch[nt][i]=0.f; }

            auto issueB = [&](int chk){
                uint32_t sa = ring_u + (chk & 3)*RING_STAGE_B;
                cp_async16(sa + (sra*36+ska)*4, &g_sumh[(size_t)(r0+sra)*HH + chk*32 + ska]);
                cp_async16(sa + (srb*36+skb)*4, &g_sumh[(size_t)(r0+srb)*HH + chk*32 + skb]);
                cp_async16(sa + 9216 + (sra*36+ska)*4, &g_sumg[(size_t)(r0+sra)*HH + chk*32 + ska]);
                cp_async16(sa + 9216 + (srb*36+skb)*4, &g_sumg[(size_t)(r0+srb)*HH + chk*32 + skb]);
                cp_commit();
            };
            issueB(0); issueB(1); issueB(2);

            for (int chk=0; chk<16; chk++){
                if (chk < 14) cp_wait<2>(); else if (chk == 14) cp_wait<1>(); else cp_wait<0>();
                __syncthreads();
                if (chk+3 < 16) issueB(chk+3);

                const uint32_t* Ah = (const uint32_t*)(ringf + (chk & 3)*4608);
                const uint32_t* Ag = Ah + 2304;

                #pragma unroll
                for (int ks=0; ks<4; ks++){
                    int rb0 = wm*16 + gid;
                    uint32_t ah[4], ag[4];
                    ah[0]=Ah[rb0*36 + ks*8 + tig];     ah[1]=Ah[(rb0+8)*36 + ks*8 + tig];
                    ah[2]=Ah[rb0*36 + ks*8 + tig + 4]; ah[3]=Ah[(rb0+8)*36 + ks*8 + tig + 4];
                    ag[0]=Ag[rb0*36 + ks*8 + tig];     ag[1]=Ag[(rb0+8)*36 + ks*8 + tig];
                    ag[2]=Ag[rb0*36 + ks*8 + tig + 4]; ag[3]=Ag[(rb0+8)*36 + ks*8 + tig + 4];
                    #pragma unroll
                    for (int nt=0; nt<2; nt++){
                        int g = ((chk*4 + ks)*2 + wn)*2 + nt;
                        uint4 wf = *(const uint4*)&WF[g*32 + lane];
                        uint32_t bz[2] = {wf.x, wf.y};
                        uint32_t bh[2] = {wf.z, wf.w};
                        mma_tf32(accz[nt], ah, bz);
                        mma_tf32(acch[nt], ag, bh);
                    }
                }
            }

            #pragma unroll
            for (int nt=0; nt<2; nt++){
                #pragma unroll
                for (int half=0; half<2; half++){
                    int b   = r0 + wm*16 + gid + half*8;
                    int col = c0 + wn*16 + nt*8 + tig*2;
                    size_t xi = ((size_t)b*TT + t)*HH + col;
                    float2 xz = *(const float2*)&g_Xz[xi];
                    float2 xh = *(const float2*)&g_Xh[xi];
                    float2 sh = __ldcg((const float2*)&g_sumh[(size_t)b*HH + col]);
                    float z0 = sigf(xz.x + accz[nt][half*2+0]);
                    float z1 = sigf(xz.y + accz[nt][half*2+1]);
                    float p0 = tanhf(xh.x + acch[nt][half*2+0]);
                    float p1 = tanhf(xh.y + acch[nt][half*2+1]);
                    float2 out;
                    out.x = (1.f - z0)*sh.x + z0*p0;
                    out.y = (1.f - z1)*sh.y + z1*p1;
                    *(float2*)&g_pair[((size_t)b*TT + t + 1)*PW + col] = out;
                }
            }
        }
        gsync(epoch);

        if (t == TT-1) break;

        // ---- phase C: Uh(step-t rows) = new_h @ Ur ----
        {
            float accu[2][4];
            #pragma unroll
            for (int nt=0;nt<2;nt++)
                #pragma unroll
                for (int i=0;i<4;i++) accu[nt][i]=0.f;

            auto issueC = [&](int chk){
                uint32_t sa = ring_u + (chk & 3)*RING_STAGE_B;
                cp_async16(sa + (sra*36+ska)*4, &g_pair[((size_t)(r0+sra)*TT + t + 1)*PW + chk*32 + ska]);
                cp_async16(sa + (srb*36+skb)*4, &g_pair[((size_t)(r0+srb)*TT + t + 1)*PW + chk*32 + skb]);
                cp_async16(sa + 9216 + (ur_r*40 + ur_c)*4, &Ur[(size_t)(chk*32 + ur_r)*HH + c0 + ur_c]);
                cp_commit();
            };
            issueC(0); issueC(1); issueC(2);

            for (int chk=0; chk<16; chk++){
                if (chk < 14) cp_wait<2>(); else if (chk == 14) cp_wait<1>(); else cp_wait<0>();
                __syncthreads();
                if (chk+3 < 16) issueC(chk+3);

                const uint32_t* Ah = (const uint32_t*)(ringf + (chk & 3)*4608);
                const uint32_t* Uc = Ah + 2304;   // [32][40]

                #pragma unroll
                for (int ks=0; ks<4; ks++){
                    int rb0 = wm*16 + gid;
                    uint32_t ah[4];
                    ah[0]=Ah[rb0*36 + ks*8 + tig];     ah[1]=Ah[(rb0+8)*36 + ks*8 + tig];
                    ah[2]=Ah[rb0*36 + ks*8 + tig + 4]; ah[3]=Ah[(rb0+8)*36 + ks*8 + tig + 4];
                    #pragma unroll
                    for (int nt=0; nt<2; nt++){
                        int n = wn*16 + nt*8 + gid;
                        uint32_t bu[2];
                        bu[0] = Uc[(ks*8 + tig)*40 + n];
                        bu[1] = Uc[(ks*8 + tig + 4)*40 + n];
                        mma_tf32(accu[nt], ah, bu);
                    }
                }
            }

            #pragma unroll
            for (int nt=0; nt<2; nt++){
                #pragma unroll
                for (int half=0; half<2; half++){
                    int b   = r0 + wm*16 + gid + half*8;
                    int col = c0 + wn*16 + nt*8 + tig*2;
                    float2 out;
                    out.x = accu[nt][half*2+0];
                    out.y = accu[nt][half*2+1];
                    *(float2*)&g_pair[((size_t)b*TT + t + 1)*PW + 512 + col] = out;
                }
            }
        }
        gsync(epoch);
    }
}

// ---------------- deferred o gather (o-half only) ----------------
__global__ void k_oall(const int* __restrict__ nei_o, const int* __restrict__ root_nei)
{
    int i = blockIdx.x;
    int c = blockIdx.y*256 + threadIdx.x;
    if (i < BT) {
        int tt = i % TT;
        const int* idx = nei_o + (size_t)i*MAX_NB;
        float o = 0.f;
        #pragma unroll
        for (int n=0;n<MAX_NB;n++){
            int id = idx[n];
            if (id > 0 && ((id-1) % TT) < tt) o += g_pair[(size_t)id*PW + c];
        }
        g_stopO[(size_t)i*HH + c] = o;
    } else {
        int b = i - BT;
        const int* idx = root_nei + (size_t)b*MAX_NB;
        float o = 0.f;
        #pragma unroll
        for (int n=0;n<MAX_NB;n++) o += g_pair[(size_t)idx[n]*PW + c];
        g_stopO[(size_t)i*HH + c] = o;
    }
}

// ---------------- stop loss / acc ----------------
__global__ void k_stoploss(const int* __restrict__ direction, const float* __restrict__ usb)
{
    int i = blockIdx.x*256 + threadIdx.x;
    float li = 0.f, ci = 0.f;
    if (i < NSTOP){
        float s = g_score[i] + usb[0];
        float tgt = (i < BT) ? (float)direction[i] : 0.f;
        float sp = (s > 0.f) ? (s + log1pf(expf(-s))) : log1pf(expf(s));
        li = sp - s*tgt;
        float pred = (s >= 0.f) ? 1.f : 0.f;
        ci = (pred == tgt) ? 1.f : 0.f;
    }
    __shared__ float rl[256], rc[256];
    rl[threadIdx.x]=li; rc[threadIdx.x]=ci;
    __syncthreads();
    for (int st=128; st>0; st>>=1){
        if (threadIdx.x < st){ rl[threadIdx.x]+=rl[threadIdx.x+st]; rc[threadIdx.x]+=rc[threadIdx.x+st]; }
        __syncthreads();
    }
    if (threadIdx.x==0){
        atomicAdd(&g_red[3], rl[0]);
        atomicAdd(&g_red[4], rc[0]);
    }
}

// ---------------- pred head CE / acc over compacted rows ----------------
__global__ void k_ce(const int* __restrict__ target)
{
    int slot = blockIdx.x;
    if (slot >= g_cnt) return;
    int i = g_list[slot];
    int t = threadIdx.x;
    const float* S = g_predS + (size_t)slot*VV;
    float val[4];
    float lmax = -1e30f; int lidx = 0;
    #pragma unroll
    for (int r=0;r<4;r++){
        int v = t + 256*r;
        if (v < VV){
            float x = S[v];
            val[r] = x;
            if (x > lmax){ lmax = x; lidx = v; }
        } else val[r] = -1e30f;
    }
    __shared__ float smax[256]; __shared__ int sidx[256];
    smax[t]=lmax; sidx[t]=lidx;
    __syncthreads();
    for (int st=128; st>0; st>>=1){
        if (t < st){
            float o = smax[t+st]; int oi = sidx[t+st];
            if (o > smax[t] || (o == smax[t] && oi < sidx[t])){ smax[t]=o; sidx[t]=oi; }
        }
        __syncthreads();
    }
    float m = smax[0]; int am = sidx[0];
    __syncthreads();
    float se = 0.f;
    #pragma unroll
    for (int r=0;r<4;r++){
        int v = t + 256*r;
        if (v < VV) se += expf(val[r] - m);
    }
    __shared__ float ssum[256];
    ssum[t]=se;
    __syncthreads();
    for (int st=128; st>0; st>>=1){
        if (t < st) ssum[t]+=ssum[t+st];
        __syncthreads();
    }
    if (t==0){
        float lse = m + logf(ssum[0]);
        int tg = target[i];
        float ce = lse - S[tg];
        atomicAdd(&g_red[0], ce);
        atomicAdd(&g_red[1], (am==tg) ? 1.f : 0.f);
        atomicAdd(&g_red[2], 1.f);
    }
}

__global__ void k_final(float* out)
{
    out[0] = g_red[0] / (float)BB;
    out[1] = g_red[3] / (float)BB;
    out[2] = g_red[1] / g_red[2];
    out[3] = g_red[4] / (float)NSTOP;
}

// ---------------- host launch ----------------
extern "C" void kernel_launch(void* const* d_in, const int* in_sizes, int n_in,
                              void* d_out, int out_size)
{
    const float* node_rep = (const float*)d_in[0];
    const int*   clique   = (const int*)  d_in[1];
    const int*   rclique  = (const int*)  d_in[2];
    const int*   nei_h    = (const int*)  d_in[3];
    const int*   nei_o    = (const int*)  d_in[4];
    const int*   rnei     = (const int*)  d_in[5];
    const int*   dir      = (const int*)  d_in[6];
    const int*   ptgt     = (const int*)  d_in[7];
    const float* Wz  = (const float*)d_in[8];
    const float* Wzb = (const float*)d_in[9];
    const float* Wr  = (const float*)d_in[10];
    const float* Wrb = (const float*)d_in[11];
    const float* Ur  = (const float*)d_in[12];
    const float* Wh  = (const float*)d_in[13];
    const float* Whb = (const float*)d_in[14];
    const float* Ww  = (const float*)d_in[15];
    const float* Wwb = (const float*)d_in[16];
    const float* Uw  = (const float*)d_in[17];
    const float* Ub  = (const float*)d_in[18];
    const float* Wo  = (const float*)d_in[19];
    const float* Wob = (const float*)d_in[20];
    const float* Us  = (const float*)d_in[21];
    const float* Usb = (const float*)d_in[22];

    float *pair, *nZ, *nR, *nH, *nS, *stopO, *stopX, *predH, *predS, *score, *red;
    unsigned* bar; int* cnt; int* list;
    cudaGetSymbolAddress((void**)&pair,  g_pair);
    cudaGetSymbolAddress((void**)&nZ,    g_nodeZ);
    cudaGetSymbolAddress((void**)&nR,    g_nodeR);
    cudaGetSymbolAddress((void**)&nH,    g_nodeH);
    cudaGetSymbolAddress((void**)&nS,    g_nodeS);
    cudaGetSymbolAddress((void**)&stopO, g_stopO);
    cudaGetSymbolAddress((void**)&stopX, g_stopX);
    cudaGetSymbolAddress((void**)&predH, g_predH);
    cudaGetSymbolAddress((void**)&predS, g_predS);
    cudaGetSymbolAddress((void**)&score, g_score);
    cudaGetSymbolAddress((void**)&red,   g_red);
    cudaGetSymbolAddress((void**)&bar,   g_bar);
    cudaGetSymbolAddress((void**)&cnt,   g_cnt);
    cudaGetSymbolAddress((void**)&list,  g_list);

    static int attr_set = 0;
    if (!attr_set){
        cudaFuncSetAttribute(k_scan, cudaFuncAttributeMaxDynamicSharedMemorySize, SMEM_SCAN);
        cudaFuncSetAttribute(tgemm<3,false,true,0>,  cudaFuncAttributeMaxDynamicSharedMemorySize, SMEM_TG);
        cudaFuncSetAttribute(tgemm<2,false,false,0>, cudaFuncAttributeMaxDynamicSharedMemorySize, SMEM_TG);
        cudaFuncSetAttribute(tgemm<1,false,false,1>, cudaFuncAttributeMaxDynamicSharedMemorySize, SMEM_TG);
        cudaFuncSetAttribute(tgemm<0,true,false,2>,  cudaFuncAttributeMaxDynamicSharedMemorySize, SMEM_TG);
        attr_set = 1;
    }

    cudaMemsetAsync(pair, 0, sizeof(float)*(size_t)NMSG*PW);
    cudaMemsetAsync(score,0, sizeof(float)*NSTOP);
    cudaMemsetAsync(red,  0, sizeof(float)*8);
    cudaMemsetAsync(bar,  0, sizeof(unsigned));
    cudaMemsetAsync(cnt,  0, sizeof(int));
    cudaMemsetAsync(list, 0, sizeof(int)*BT);

    // node-level projections (Wz_x, Wr, Wh_x, Uw_x) in one launch
    dim3 gN(4, (BB*N_AT)/128, 4);
    tgemm<3,false,true,0><<<gN, 256, SMEM_TG>>>(node_rep, HH, Wz, HH, nullptr, nZ, HH,
                                                HH, HH, nullptr, nullptr,
                                                Wr, Wh, Uw, nR, nH, nS);
    k_xproj<<<BT, 256>>>(clique, Wzb, Wrb, Whb);
    k_rootS<<<BB, 256>>>(rclique);
    k_compact<<<BT/256, 256>>>(dir);

    // sequential scan
    const float* Wzh = Wz + (size_t)HH*HH;
    const float* Whh = Wh + (size_t)HH*HH;
    k_scan<<<NBLK, 256, SMEM_SCAN>>>(nei_h, Wzh, Whh, Ur);

    // stop head
    k_oall<<<dim3(NSTOP,2), 256>>>(nei_o, rnei);
    tgemm<2,false,false,0><<<dim3(4, NSTOP/128), 256, SMEM_TG>>>(stopO, HH,
        Uw + (size_t)HH*HH, HH, Ub, nullptr, 0, HH, HH, Us, stopX,
        nullptr, nullptr, nullptr, nullptr, nullptr, nullptr);
    k_stoploss<<<NSTOP/256, 256>>>(dir, Usb);

    // pred head over compacted rows (A rows = pair h-halves, rows 1..BT, lda=PW)
    tgemm<1,false,false,1><<<dim3(4, BT/128), 256, SMEM_TG>>>(pair + PW, PW, Ww, HH, Wwb,
        predH, HH, HH, HH, nullptr, nullptr,
        nullptr, nullptr, nullptr, nullptr, nullptr, nullptr);
    tgemm<0,true,false,2><<<dim3(7, BT/128), 256, SMEM_TG>>>(predH, HH, Wo, VV, Wob,
        predS, VV, VV, HH, nullptr, nullptr,
        nullptr, nullptr, nullptr, nullptr, nullptr, nullptr);
    k_ce<<<BT, 256>>>(ptgt);

    k_final<<<1,1>>>((float*)d_out);
}

// round 15
// speedup vs baseline: 1.6995x; 1.1453x over previous
#include <cuda_runtime.h>
#include <cuda_bf16.h>
#include <math.h>
#include <stdint.h>

#define BB 512
#define TT 64
#define HH 512
#define VV 780
#define N_AT 40
#define KC 4
#define MAX_NB 8
#define NMSG (BB*TT+1)
#define BT (BB*TT)
#define NSTOP (BT+BB)
#define H2 (2*HH)
#define NBLK 128
#define PW 1024   // pair row width: [h(512) | Uh(512)]

// k_scan smem: packed weight fragments (128KB) + 4-stage ring (72KB)
#define WF_FLOATS (16*4*2*2*32*4)     // 32768 floats = 128KB
#define RING_STAGE_B 18432
#define SMEM_SCAN (WF_FLOATS*4 + 4*RING_STAGE_B)   // 204800 B

// tgemm: 3-stage ring of (A[128][36] + B[32][132]) fp32 tiles
#define TG_ABUF (128*36)
#define TG_BBUF (32*132)
#define TG_STAGE (TG_ABUF + TG_BBUF)
#define SMEM_TG (3*TG_STAGE*4)

// ---------------- device scratch ----------------
__device__ float g_pair  [(size_t)NMSG*PW];
__device__ float g_nodeZ [BB*N_AT*HH];
__device__ float g_nodeR [BB*N_AT*HH];
__device__ float g_nodeH [BB*N_AT*HH];
__device__ float g_nodeS [BB*N_AT*HH];
__device__ float g_Xz    [BT*HH];
__device__ float g_Xr    [BT*HH];
__device__ float g_Xh    [BT*HH];
__device__ float g_sumh  [BB*HH];
__device__ float g_sumg  [BB*HH];
__device__ float g_stopO [NSTOP*HH];
__device__ float g_stopX [NSTOP*HH];
__device__ float g_predH [BT*HH];
__device__ float g_predS [BT*VV];
__device__ float g_score [NSTOP];
__device__ float g_red   [8];
__device__ unsigned g_bar;
__device__ int g_cnt;
__device__ int g_list[BT];

__device__ __forceinline__ float sigf(float x){ return 1.f/(1.f+expf(-x)); }

__device__ __forceinline__ void cp_async16(uint32_t dst, const void* src){
    asm volatile("cp.async.cg.shared.global [%0], [%1], 16;\n" :: "r"(dst), "l"(src));
}
__device__ __forceinline__ void cp_async16z(uint32_t dst, const void* src, int bytes){
    asm volatile("cp.async.cg.shared.global [%0], [%1], 16, %2;\n" :: "r"(dst), "l"(src), "r"(bytes));
}
__device__ __forceinline__ void cp_commit(){ asm volatile("cp.async.commit_group;\n"); }
template<int N> __device__ __forceinline__ void cp_wait(){ asm volatile("cp.async.wait_group %0;\n" :: "n"(N)); }

__device__ __forceinline__ void mma_tf32(float* d, const uint32_t* a, const uint32_t* b){
    asm volatile(
        "mma.sync.aligned.m16n8k8.row.col.f32.tf32.tf32.f32 "
        "{%0,%1,%2,%3},{%4,%5,%6,%7},{%8,%9},{%0,%1,%2,%3};\n"
        : "+f"(d[0]), "+f"(d[1]), "+f"(d[2]), "+f"(d[3])
        : "r"(a[0]), "r"(a[1]), "r"(a[2]), "r"(a[3]), "r"(b[0]), "r"(b[1]));
}

// ---------------- gather node projections (float4, split arrays) ----------------
__global__ void k_xproj(const int* __restrict__ cidx,
                        const float* __restrict__ bz,
                        const float* __restrict__ br,
                        const float* __restrict__ bh)
{
    int i = blockIdx.x;
    int b = i / TT;
    const int* ci = cidx + (size_t)i*KC;
    int r0 = b*N_AT;
    const int grp = threadIdx.x >> 7;          // 0: Z/R  1: H/S
    const int c4 = (threadIdx.x & 127) * 4;

    float4 a0, a1;
    if (grp == 0){
        a0 = *(const float4*)&bz[c4];
        a1 = *(const float4*)&br[c4];
    } else {
        a0 = *(const float4*)&bh[c4];
        a1 = make_float4(0.f,0.f,0.f,0.f);
    }
    const float* A0 = grp ? g_nodeH : g_nodeZ;
    const float* A1 = grp ? g_nodeS : g_nodeR;
    #pragma unroll
    for (int k=0;k<KC;k++){
        size_t row = (size_t)(r0 + ci[k])*HH + c4;
        float4 v0 = *(const float4*)&A0[row];
        float4 v1 = *(const float4*)&A1[row];
        a0.x+=v0.x; a0.y+=v0.y; a0.z+=v0.z; a0.w+=v0.w;
        a1.x+=v1.x; a1.y+=v1.y; a1.z+=v1.z; a1.w+=v1.w;
    }
    if (grp == 0){
        *(float4*)&g_Xz[(size_t)i*HH + c4] = a0;
        *(float4*)&g_Xr[(size_t)i*HH + c4] = a1;
    } else {
        *(float4*)&g_Xh[(size_t)i*HH + c4] = a0;
        *(float4*)&g_stopX[(size_t)i*HH + c4] = a1;
    }
}

__global__ void k_rootS(const int* __restrict__ rcidx)
{
    int b = blockIdx.x;
    const int* ci = rcidx + (size_t)b*KC;
    #pragma unroll
    for (int cc=0; cc<2; cc++){
        int c = threadIdx.x + cc*256;
        float ss = 0.f;
        #pragma unroll
        for (int k=0;k<KC;k++)
            ss += g_nodeS[(size_t)(b*N_AT + ci[k])*HH + c];
        g_stopX[(size_t)(BT + b)*HH + c] = ss;
    }
}

__global__ void k_compact(const int* __restrict__ direction)
{
    int i = blockIdx.x*256 + threadIdx.x;
    if (i < BT && direction[i] == 1){
        int s = atomicAdd(&g_cnt, 1);
        g_list[s] = i;
    }
}

// ---------------- tf32 tensor-core GEMM ----------------
template<int EPI, bool NG, bool ZSEL, int GMODE>
__global__ void __launch_bounds__(256)
tgemm(const float* __restrict__ A, int lda,
      const float* __restrict__ Bm0, int ldb,
      const float* __restrict__ bias,
      float* __restrict__ C0, int ldc,
      int N, int K,
      const float* __restrict__ us,
      const float* __restrict__ xadd,
      const float* Bm1, const float* Bm2, const float* Bm3,
      float* C1, float* C2, float* C3)
{
    extern __shared__ float dynsm[];
    const int by = blockIdx.y, bx = blockIdx.x;
    const int rowb = by*128, colb = bx*128;
    if (GMODE){ if (rowb >= g_cnt) return; }

    const int tid  = threadIdx.x;
    const int warp = tid >> 5, lane = tid & 31;
    const int wm = warp & 3, wn = warp >> 2;
    const int gid = lane >> 2, tig = lane & 3;

    const float* Bm = Bm0;
    float* C = C0;
    if (ZSEL){
        if (blockIdx.z == 1){ Bm = Bm1; C = C1; }
        else if (blockIdx.z == 2){ Bm = Bm2; C = C2; }
        else if (blockIdx.z == 3){ Bm = Bm3; C = C3; }
    }

    uint32_t smem_base = (uint32_t)__cvta_generic_to_shared(dynsm);

    float acc[2][8][4];
    #pragma unroll
    for (int mt=0;mt<2;mt++)
        #pragma unroll
        for (int nt=0;nt<8;nt++)
            #pragma unroll
            for (int i=0;i<4;i++) acc[mt][nt][i]=0.f;

    const int nk = K >> 5;

    auto issue = [&](int kt, int stage){
        uint32_t sa = smem_base + stage*TG_STAGE*4;
        uint32_t sb = sa + TG_ABUF*4;
        #pragma unroll
        for (int i=0;i<4;i++){
            int q = tid + 256*i;
            int r = q >> 3, k4 = (q & 7)*4;
            size_t arow = (GMODE == 1) ? (size_t)g_list[rowb + r] : (size_t)(rowb + r);
            cp_async16(sa + (r*36 + k4)*4, A + arow*lda + kt*32 + k4);
        }
        #pragma unroll
        for (int i=0;i<4;i++){
            int q = tid + 256*i;
            int kr = q >> 5, n4 = (q & 31)*4;
            uint32_t dst = sb + (kr*132 + n4)*4;
            if (NG){
                int col = colb + n4;
                int bytes = (col + 3 < N) ? 16 : ((col < N) ? (N - col)*4 : 0);
                const float* src = Bm + (size_t)(kt*32 + kr)*ldb + (bytes ? col : 0);
                cp_async16z(dst, src, bytes);
            } else {
                cp_async16(dst, Bm + (size_t)(kt*32 + kr)*ldb + colb + n4);
            }
        }
        cp_commit();
    };

    issue(0, 0);
    if (nk > 1) issue(1, 1);

    for (int it=0; it<nk; it++){
        if (it+2 < nk) issue(it+2, (it+2)%3);
        if (it+1 < nk) cp_wait<1>(); else cp_wait<0>();
        __syncthreads();

        const uint32_t* As = (const uint32_t*)(dynsm + (it%3)*TG_STAGE);
        const uint32_t* Bs = (const uint32_t*)(dynsm + (it%3)*TG_STAGE + TG_ABUF);

        #pragma unroll
        for (int ks=0; ks<4; ks++){
            uint32_t af[2][4];
            #pragma unroll
            for (int mt=0; mt<2; mt++){
                int r = wm*32 + mt*16 + gid;
                af[mt][0] = As[r*36 + ks*8 + tig];
                af[mt][1] = As[(r+8)*36 + ks*8 + tig];
                af[mt][2] = As[r*36 + ks*8 + tig + 4];
                af[mt][3] = As[(r+8)*36 + ks*8 + tig + 4];
            }
            uint32_t bf[8][2];
            #pragma unroll
            for (int nt=0; nt<8; nt++){
                int n = wn*64 + nt*8 + gid;
                bf[nt][0] = Bs[(ks*8 + tig)*132 + n];
                bf[nt][1] = Bs[(ks*8 + tig + 4)*132 + n];
            }
            #pragma unroll
            for (int mt=0; mt<2; mt++)
                #pragma unroll
                for (int nt=0; nt<8; nt++)
                    mma_tf32(acc[mt][nt], af[mt], bf[nt]);
        }
        __syncthreads();
    }

    if (EPI == 2){
        #pragma unroll
        for (int mt=0; mt<2; mt++){
            int row0 = rowb + wm*32 + mt*16 + gid;
            float s0 = 0.f, s1 = 0.f;
            #pragma unroll
            for (int nt=0; nt<8; nt++){
                int col = colb + wn*64 + nt*8 + 2*tig;
                float b0 = bias[col], b1 = bias[col+1];
                float u0 = us[col],  u1 = us[col+1];
                float2 x0 = *(const float2*)&xadd[(size_t)row0*HH + col];
                float2 x1 = *(const float2*)&xadd[(size_t)(row0+8)*HH + col];
                float v;
                v = acc[mt][nt][0] + b0 + x0.x; s0 += (v>0.f? v:0.f)*u0;
                v = acc[mt][nt][1] + b1 + x0.y; s0 += (v>0.f? v:0.f)*u1;
                v = acc[mt][nt][2] + b0 + x1.x; s1 += (v>0.f? v:0.f)*u0;
                v = acc[mt][nt][3] + b1 + x1.y; s1 += (v>0.f? v:0.f)*u1;
            }
            s0 += __shfl_xor_sync(0xffffffffu, s0, 1);
            s0 += __shfl_xor_sync(0xffffffffu, s0, 2);
            s1 += __shfl_xor_sync(0xffffffffu, s1, 1);
            s1 += __shfl_xor_sync(0xffffffffu, s1, 2);
            if (tig == 0){
                atomicAdd(&g_score[row0], s0);
                atomicAdd(&g_score[row0+8], s1);
            }
        }
    } else {
        #pragma unroll
        for (int mt=0; mt<2; mt++){
            #pragma unroll
            for (int nt=0; nt<8; nt++){
                int col = colb + wn*64 + nt*8 + 2*tig;
                int row = rowb + wm*32 + mt*16 + gid;
                #pragma unroll
                for (int i=0; i<4; i++){
                    int cc = col + (i & 1);
                    int rr = row + ((i >> 1) ? 8 : 0);
                    if (!NG || cc < N){
                        float v = acc[mt][nt][i];
                        if (EPI != 3) v += bias[cc];
                        if (EPI == 1) v = v > 0.f ? v : 0.f;
                        C[(size_t)rr*ldc + cc] = v;
                    }
                }
            }
        }
    }
}

// ---------------- persistent scan kernel ----------------
__device__ __forceinline__ void gsync(int& epoch)
{
    __syncthreads();
    if (threadIdx.x == 0){
        __threadfence();
        atomicAdd(&g_bar, 1u);
        unsigned tgt = (unsigned)epoch * NBLK;
        while (*((volatile unsigned*)&g_bar) < tgt) { }
    }
    epoch++;
    __syncthreads();
}

__global__ void __launch_bounds__(256, 1)
k_scan(const int* __restrict__ nei_h,
       const float* __restrict__ Wzh,
       const float* __restrict__ Whh,
       const float* __restrict__ Ur)
{
    extern __shared__ float smem[];
    float4* WF  = (float4*)smem;
    float* ringf = smem + WF_FLOATS;

    const int tid = threadIdx.x;
    const int blk = blockIdx.x;
    const int rt = blk >> 4, ct = blk & 15;
    const int r0 = rt*64, c0 = ct*32;
    const int warp = tid >> 5, lane = tid & 31;
    const int wm = warp & 3, wn = warp >> 2;
    const int gid = lane >> 2, tig = lane & 3;
    const int id4a = tid*2, id4b = tid*2+1;
    const int sra = id4a >> 3, ska = (id4a & 7)*4;
    const int srb = id4b >> 3, skb = (id4b & 7)*4;
    const int ur_r = tid >> 3, ur_c = (tid & 7)*4;
    // phase-A float4 mapping
    const int arow = tid >> 7;            // 0..1
    const int ac4  = (tid & 127) * 4;

    const uint32_t ring_u = (uint32_t)__cvta_generic_to_shared(ringf);

    for (int g = warp; g < 256; g += 8){
        int nt  = g & 1, wns = (g >> 1) & 1, ks = (g >> 2) & 3, chunk = g >> 4;
        int krow = chunk*32 + ks*8 + tig;
        int col  = c0 + wns*16 + nt*8 + gid;
        float4 v;
        v.x = Wzh[(size_t)krow*HH + col];
        v.y = Wzh[(size_t)(krow+4)*HH + col];
        v.z = Whh[(size_t)krow*HH + col];
        v.w = Whh[(size_t)(krow+4)*HH + col];
        WF[g*32 + lane] = v;
    }
    __syncthreads();

    int epoch = 1;

    for (int t = 0; t < TT; t++){
        // ---- phase A: gather sum_h, sum_g (float4, pair rows) ----
        #pragma unroll
        for (int pass=0; pass<2; pass++){
            int b = blk*4 + pass*2 + arow;
            const int* idx = nei_h + ((size_t)b*TT + t)*MAX_NB;
            const float* pr[8];
            #pragma unroll
            for (int n=0;n<8;n++) pr[n] = g_pair + (size_t)idx[n]*PW;
            float4 xr = *(const float4*)&g_Xr[((size_t)b*TT + t)*HH + ac4];
            float4 ah = make_float4(0.f,0.f,0.f,0.f);
            float4 ag = make_float4(0.f,0.f,0.f,0.f);
            #pragma unroll
            for (int n=0;n<8;n++){
                float4 hv = __ldcg((const float4*)(pr[n] + ac4));
                float4 uv = __ldcg((const float4*)(pr[n] + 512 + ac4));
                ah.x += hv.x; ah.y += hv.y; ah.z += hv.z; ah.w += hv.w;
                ag.x += hv.x * sigf(xr.x + uv.x);
                ag.y += hv.y * sigf(xr.y + uv.y);
                ag.z += hv.z * sigf(xr.z + uv.z);
                ag.w += hv.w * sigf(xr.w + uv.w);
            }
            *(float4*)&g_sumh[b*HH+ac4] = ah;
            *(float4*)&g_sumg[b*HH+ac4] = ag;
        }
        gsync(epoch);

        // ---- phase B: dual tf32 GEMM + GRU epilogue ----
        {
            float accz[2][4], acch[2][4];
            #pragma unroll
            for (int nt=0;nt<2;nt++)
                #pragma unroll
                for (int i=0;i<4;i++){ accz[nt][i]=0.f; acch[nt][i]=0.f; }

            auto issueB = [&](int chk){
                uint32_t sa = ring_u + (chk & 3)*RING_STAGE_B;
                cp_async16(sa + (sra*36+ska)*4, &g_sumh[(size_t)(r0+sra)*HH + chk*32 + ska]);
                cp_async16(sa + (srb*36+skb)*4, &g_sumh[(size_t)(r0+srb)*HH + chk*32 + skb]);
                cp_async16(sa + 9216 + (sra*36+ska)*4, &g_sumg[(size_t)(r0+sra)*HH + chk*32 + ska]);
                cp_async16(sa + 9216 + (srb*36+skb)*4, &g_sumg[(size_t)(r0+srb)*HH + chk*32 + skb]);
                cp_commit();
            };
            issueB(0); issueB(1); issueB(2);

            for (int chk=0; chk<16; chk++){
                if (chk < 14) cp_wait<2>(); else if (chk == 14) cp_wait<1>(); else cp_wait<0>();
                __syncthreads();
                if (chk+3 < 16) issueB(chk+3);

                const uint32_t* Ah = (const uint32_t*)(ringf + (chk & 3)*4608);
                const uint32_t* Ag = Ah + 2304;

                #pragma unroll
                for (int ks=0; ks<4; ks++){
                    int rb0 = wm*16 + gid;
                    uint32_t ah[4], ag[4];
                    ah[0]=Ah[rb0*36 + ks*8 + tig];     ah[1]=Ah[(rb0+8)*36 + ks*8 + tig];
                    ah[2]=Ah[rb0*36 + ks*8 + tig + 4]; ah[3]=Ah[(rb0+8)*36 + ks*8 + tig + 4];
                    ag[0]=Ag[rb0*36 + ks*8 + tig];     ag[1]=Ag[(rb0+8)*36 + ks*8 + tig];
                    ag[2]=Ag[rb0*36 + ks*8 + tig + 4]; ag[3]=Ag[(rb0+8)*36 + ks*8 + tig + 4];
                    #pragma unroll
                    for (int nt=0; nt<2; nt++){
                        int g = ((chk*4 + ks)*2 + wn)*2 + nt;
                        uint4 wf = *(const uint4*)&WF[g*32 + lane];
                        uint32_t bz[2] = {wf.x, wf.y};
                        uint32_t bh[2] = {wf.z, wf.w};
                        mma_tf32(accz[nt], ah, bz);
                        mma_tf32(acch[nt], ag, bh);
                    }
                }
            }

            #pragma unroll
            for (int nt=0; nt<2; nt++){
                #pragma unroll
                for (int half=0; half<2; half++){
                    int b   = r0 + wm*16 + gid + half*8;
                    int col = c0 + wn*16 + nt*8 + tig*2;
                    size_t xi = ((size_t)b*TT + t)*HH + col;
                    float2 xz = *(const float2*)&g_Xz[xi];
                    float2 xh = *(const float2*)&g_Xh[xi];
                    float2 sh = __ldcg((const float2*)&g_sumh[(size_t)b*HH + col]);
                    float z0 = sigf(xz.x + accz[nt][half*2+0]);
                    float z1 = sigf(xz.y + accz[nt][half*2+1]);
                    float p0 = tanhf(xh.x + acch[nt][half*2+0]);
                    float p1 = tanhf(xh.y + acch[nt][half*2+1]);
                    float2 out;
                    out.x = (1.f - z0)*sh.x + z0*p0;
                    out.y = (1.f - z1)*sh.y + z1*p1;
                    *(float2*)&g_pair[((size_t)b*TT + t + 1)*PW + col] = out;
                }
            }
        }
        gsync(epoch);

        if (t == TT-1) break;

        // ---- phase C: Uh(step-t rows) = new_h @ Ur ----
        {
            float accu[2][4];
            #pragma unroll
            for (int nt=0;nt<2;nt++)
                #pragma unroll
                for (int i=0;i<4;i++) accu[nt][i]=0.f;

            auto issueC = [&](int chk){
                uint32_t sa = ring_u + (chk & 3)*RING_STAGE_B;
                cp_async16(sa + (sra*36+ska)*4, &g_pair[((size_t)(r0+sra)*TT + t + 1)*PW + chk*32 + ska]);
                cp_async16(sa + (srb*36+skb)*4, &g_pair[((size_t)(r0+srb)*TT + t + 1)*PW + chk*32 + skb]);
                cp_async16(sa + 9216 + (ur_r*40 + ur_c)*4, &Ur[(size_t)(chk*32 + ur_r)*HH + c0 + ur_c]);
                cp_commit();
            };
            issueC(0); issueC(1); issueC(2);

            for (int chk=0; chk<16; chk++){
                if (chk < 14) cp_wait<2>(); else if (chk == 14) cp_wait<1>(); else cp_wait<0>();
                __syncthreads();
                if (chk+3 < 16) issueC(chk+3);

                const uint32_t* Ah = (const uint32_t*)(ringf + (chk & 3)*4608);
                const uint32_t* Uc = Ah + 2304;

                #pragma unroll
                for (int ks=0; ks<4; ks++){
                    int rb0 = wm*16 + gid;
                    uint32_t ah[4];
                    ah[0]=Ah[rb0*36 + ks*8 + tig];     ah[1]=Ah[(rb0+8)*36 + ks*8 + tig];
                    ah[2]=Ah[rb0*36 + ks*8 + tig + 4]; ah[3]=Ah[(rb0+8)*36 + ks*8 + tig + 4];
                    #pragma unroll
                    for (int nt=0; nt<2; nt++){
                        int n = wn*16 + nt*8 + gid;
                        uint32_t bu[2];
                        bu[0] = Uc[(ks*8 + tig)*40 + n];
                        bu[1] = Uc[(ks*8 + tig + 4)*40 + n];
                        mma_tf32(accu[nt], ah, bu);
                    }
                }
            }

            #pragma unroll
            for (int nt=0; nt<2; nt++){
                #pragma unroll
                for (int half=0; half<2; half++){
                    int b   = r0 + wm*16 + gid + half*8;
                    int col = c0 + wn*16 + nt*8 + tig*2;
                    float2 out;
                    out.x = accu[nt][half*2+0];
                    out.y = accu[nt][half*2+1];
                    *(float2*)&g_pair[((size_t)b*TT + t + 1)*PW + 512 + col] = out;
                }
            }
        }
        gsync(epoch);
    }
}

// ---------------- deferred o gather (o-half only) ----------------
__global__ void k_oall(const int* __restrict__ nei_o, const int* __restrict__ root_nei)
{
    int i = blockIdx.x;
    int c = blockIdx.y*256 + threadIdx.x;
    if (i < BT) {
        int tt = i % TT;
        const int* idx = nei_o + (size_t)i*MAX_NB;
        float o = 0.f;
        #pragma unroll
        for (int n=0;n<MAX_NB;n++){
            int id = idx[n];
            if (id > 0 && ((id-1) % TT) < tt) o += g_pair[(size_t)id*PW + c];
        }
        g_stopO[(size_t)i*HH + c] = o;
    } else {
        int b = i - BT;
        const int* idx = root_nei + (size_t)b*MAX_NB;
        float o = 0.f;
        #pragma unroll
        for (int n=0;n<MAX_NB;n++) o += g_pair[(size_t)idx[n]*PW + c];
        g_stopO[(size_t)i*HH + c] = o;
    }
}

// ---------------- stop loss / acc ----------------
__global__ void k_stoploss(const int* __restrict__ direction, const float* __restrict__ usb)
{
    int i = blockIdx.x*256 + threadIdx.x;
    float li = 0.f, ci = 0.f;
    if (i < NSTOP){
        float s = g_score[i] + usb[0];
        float tgt = (i < BT) ? (float)direction[i] : 0.f;
        float sp = (s > 0.f) ? (s + log1pf(expf(-s))) : log1pf(expf(s));
        li = sp - s*tgt;
        float pred = (s >= 0.f) ? 1.f : 0.f;
        ci = (pred == tgt) ? 1.f : 0.f;
    }
    __shared__ float rl[256], rc[256];
    rl[threadIdx.x]=li; rc[threadIdx.x]=ci;
    __syncthreads();
    for (int st=128; st>0; st>>=1){
        if (threadIdx.x < st){ rl[threadIdx.x]+=rl[threadIdx.x+st]; rc[threadIdx.x]+=rc[threadIdx.x+st]; }
        __syncthreads();
    }
    if (threadIdx.x==0){
        atomicAdd(&g_red[3], rl[0]);
        atomicAdd(&g_red[4], rc[0]);
    }
}

// ---------------- pred head CE / acc over compacted rows ----------------
__global__ void k_ce(const int* __restrict__ target)
{
    int slot = blockIdx.x;
    if (slot >= g_cnt) return;
    int i = g_list[slot];
    int t = threadIdx.x;
    const float* S = g_predS + (size_t)slot*VV;
    float val[4];
    float lmax = -1e30f; int lidx = 0;
    #pragma unroll
    for (int r=0;r<4;r++){
        int v = t + 256*r;
        if (v < VV){
            float x = S[v];
            val[r] = x;
            if (x > lmax){ lmax = x; lidx = v; }
        } else val[r] = -1e30f;
    }
    __shared__ float smax[256]; __shared__ int sidx[256];
    smax[t]=lmax; sidx[t]=lidx;
    __syncthreads();
    for (int st=128; st>0; st>>=1){
        if (t < st){
            float o = smax[t+st]; int oi = sidx[t+st];
            if (o > smax[t] || (o == smax[t] && oi < sidx[t])){ smax[t]=o; sidx[t]=oi; }
        }
        __syncthreads();
    }
    float m = smax[0]; int am = sidx[0];
    __syncthreads();
    float se = 0.f;
    #pragma unroll
    for (int r=0;r<4;r++){
        int v = t + 256*r;
        if (v < VV) se += expf(val[r] - m);
    }
    __shared__ float ssum[256];
    ssum[t]=se;
    __syncthreads();
    for (int st=128; st>0; st>>=1){
        if (t < st) ssum[t]+=ssum[t+st];
        __syncthreads();
    }
    if (t==0){
        float lse = m + logf(ssum[0]);
        int tg = target[i];
        float ce = lse - S[tg];
        atomicAdd(&g_red[0], ce);
        atomicAdd(&g_red[1], (am==tg) ? 1.f : 0.f);
        atomicAdd(&g_red[2], 1.f);
    }
}

__global__ void k_final(float* out)
{
    out[0] = g_red[0] / (float)BB;
    out[1] = g_red[3] / (float)BB;
    out[2] = g_red[1] / g_red[2];
    out[3] = g_red[4] / (float)NSTOP;
}

// ---------------- host launch ----------------
extern "C" void kernel_launch(void* const* d_in, const int* in_sizes, int n_in,
                              void* d_out, int out_size)
{
    const float* node_rep = (const float*)d_in[0];
    const int*   clique   = (const int*)  d_in[1];
    const int*   rclique  = (const int*)  d_in[2];
    const int*   nei_h    = (const int*)  d_in[3];
    const int*   nei_o    = (const int*)  d_in[4];
    const int*   rnei     = (const int*)  d_in[5];
    const int*   dir      = (const int*)  d_in[6];
    const int*   ptgt     = (const int*)  d_in[7];
    const float* Wz  = (const float*)d_in[8];
    const float* Wzb = (const float*)d_in[9];
    const float* Wr  = (const float*)d_in[10];
    const float* Wrb = (const float*)d_in[11];
    const float* Ur  = (const float*)d_in[12];
    const float* Wh  = (const float*)d_in[13];
    const float* Whb = (const float*)d_in[14];
    const float* Ww  = (const float*)d_in[15];
    const float* Wwb = (const float*)d_in[16];
    const float* Uw  = (const float*)d_in[17];
    const float* Ub  = (const float*)d_in[18];
    const float* Wo  = (const float*)d_in[19];
    const float* Wob = (const float*)d_in[20];
    const float* Us  = (const float*)d_in[21];
    const float* Usb = (const float*)d_in[22];

    float *pair, *nZ, *nR, *nH, *nS, *stopO, *stopX, *predH, *predS, *score, *red;
    unsigned* bar; int* cnt; int* list;
    cudaGetSymbolAddress((void**)&pair,  g_pair);
    cudaGetSymbolAddress((void**)&nZ,    g_nodeZ);
    cudaGetSymbolAddress((void**)&nR,    g_nodeR);
    cudaGetSymbolAddress((void**)&nH,    g_nodeH);
    cudaGetSymbolAddress((void**)&nS,    g_nodeS);
    cudaGetSymbolAddress((void**)&stopO, g_stopO);
    cudaGetSymbolAddress((void**)&stopX, g_stopX);
    cudaGetSymbolAddress((void**)&predH, g_predH);
    cudaGetSymbolAddress((void**)&predS, g_predS);
    cudaGetSymbolAddress((void**)&score, g_score);
    cudaGetSymbolAddress((void**)&red,   g_red);
    cudaGetSymbolAddress((void**)&bar,   g_bar);
    cudaGetSymbolAddress((void**)&cnt,   g_cnt);
    cudaGetSymbolAddress((void**)&list,  g_list);

    static int attr_set = 0;
    if (!attr_set){
        cudaFuncSetAttribute(k_scan, cudaFuncAttributeMaxDynamicSharedMemorySize, SMEM_SCAN);
        cudaFuncSetAttribute(tgemm<3,false,true,0>,  cudaFuncAttributeMaxDynamicSharedMemorySize, SMEM_TG);
        cudaFuncSetAttribute(tgemm<2,false,false,0>, cudaFuncAttributeMaxDynamicSharedMemorySize, SMEM_TG);
        cudaFuncSetAttribute(tgemm<1,false,false,1>, cudaFuncAttributeMaxDynamicSharedMemorySize, SMEM_TG);
        cudaFuncSetAttribute(tgemm<0,true,false,2>,  cudaFuncAttributeMaxDynamicSharedMemorySize, SMEM_TG);
        attr_set = 1;
    }

    cudaMemsetAsync(pair, 0, sizeof(float)*(size_t)NMSG*PW);
    cudaMemsetAsync(score,0, sizeof(float)*NSTOP);
    cudaMemsetAsync(red,  0, sizeof(float)*8);
    cudaMemsetAsync(bar,  0, sizeof(unsigned));
    cudaMemsetAsync(cnt,  0, sizeof(int));
    cudaMemsetAsync(list, 0, sizeof(int)*BT);

    // node-level projections (Wz_x, Wr, Wh_x, Uw_x) in one launch
    dim3 gN(4, (BB*N_AT)/128, 4);
    tgemm<3,false,true,0><<<gN, 256, SMEM_TG>>>(node_rep, HH, Wz, HH, nullptr, nZ, HH,
                                                HH, HH, nullptr, nullptr,
                                                Wr, Wh, Uw, nR, nH, nS);
    k_xproj<<<BT, 256>>>(clique, Wzb, Wrb, Whb);
    k_rootS<<<BB, 256>>>(rclique);
    k_compact<<<BT/256, 256>>>(dir);

    // sequential scan
    const float* Wzh = Wz + (size_t)HH*HH;
    const float* Whh = Wh + (size_t)HH*HH;
    k_scan<<<NBLK, 256, SMEM_SCAN>>>(nei_h, Wzh, Whh, Ur);

    // stop head
    k_oall<<<dim3(NSTOP,2), 256>>>(nei_o, rnei);
    tgemm<2,false,false,0><<<dim3(4, NSTOP/128), 256, SMEM_TG>>>(stopO, HH,
        Uw + (size_t)HH*HH, HH, Ub, nullptr, 0, HH, HH, Us, stopX,
        nullptr, nullptr, nullptr, nullptr, nullptr, nullptr);
    k_stoploss<<<NSTOP/256, 256>>>(dir, Usb);

    // pred head over compacted rows
    tgemm<1,false,false,1><<<dim3(4, BT/128), 256, SMEM_TG>>>(pair + PW, PW, Ww, HH, Wwb,
        predH, HH, HH, HH, nullptr, nullptr,
        nullptr, nullptr, nullptr, nullptr, nullptr, nullptr);
    tgemm<0,true,false,2><<<dim3(7, BT/128), 256, SMEM_TG>>>(predH, HH, Wo, VV, Wob,
        predS, VV, VV, HH, nullptr, nullptr,
        nullptr, nullptr, nullptr, nullptr, nullptr, nullptr);
    k_ce<<<BT, 256>>>(ptgt);

    k_final<<<1,1>>>((float*)d_out);
}

// round 16
// speedup vs baseline: 1.7263x; 1.0157x over previous
#include <cuda_runtime.h>
#include <cuda_bf16.h>
#include <math.h>
#include <stdint.h>

#define BB 512
#define TT 64
#define HH 512
#define VV 780
#define N_AT 40
#define KC 4
#define MAX_NB 8
#define NMSG (BB*TT+1)
#define BT (BB*TT)
#define NSTOP (BT+BB)
#define H2 (2*HH)
#define NBLK 128
#define PW 1024   // pair row width: [h(512) | Uh(512)]

// k_scan smem: packed weight fragments (128KB) + 4-stage ring (72KB)
#define WF_FLOATS (16*4*2*2*32*4)     // 32768 floats = 128KB
#define RING_STAGE_B 18432
#define SMEM_SCAN (WF_FLOATS*4 + 4*RING_STAGE_B)   // 204800 B

// tgemm: 3-stage ring of (A[128][36] + B[32][132]) fp32 tiles
#define TG_ABUF (128*36)
#define TG_BBUF (32*132)
#define TG_STAGE (TG_ABUF + TG_BBUF)
#define SMEM_TG (3*TG_STAGE*4)

// ---------------- device scratch ----------------
__device__ float g_pair  [(size_t)NMSG*PW];
__device__ float g_nodeZ [BB*N_AT*HH];
__device__ float g_nodeR [BB*N_AT*HH];
__device__ float g_nodeH [BB*N_AT*HH];
__device__ float g_nodeS [BB*N_AT*HH];
__device__ float g_Xz    [BT*HH];
__device__ float g_Xr    [BT*HH];
__device__ float g_Xh    [BT*HH];
__device__ float g_sumh  [BB*HH];
__device__ float g_sumg  [BB*HH];
__device__ float g_stopO [NSTOP*HH];
__device__ float g_stopX [NSTOP*HH];
__device__ float g_predH [BT*HH];
__device__ float g_predS [BT*VV];
__device__ float g_score [NSTOP];
__device__ float g_red   [8];
__device__ unsigned g_bar;
__device__ int g_cnt;
__device__ int g_list[BT];

__device__ __forceinline__ float sigf(float x){ return 1.f/(1.f+expf(-x)); }

__device__ __forceinline__ void cp_async16(uint32_t dst, const void* src){
    asm volatile("cp.async.cg.shared.global [%0], [%1], 16;\n" :: "r"(dst), "l"(src));
}
__device__ __forceinline__ void cp_async16z(uint32_t dst, const void* src, int bytes){
    asm volatile("cp.async.cg.shared.global [%0], [%1], 16, %2;\n" :: "r"(dst), "l"(src), "r"(bytes));
}
__device__ __forceinline__ void cp_commit(){ asm volatile("cp.async.commit_group;\n"); }
template<int N> __device__ __forceinline__ void cp_wait(){ asm volatile("cp.async.wait_group %0;\n" :: "n"(N)); }

__device__ __forceinline__ void mma_tf32(float* d, const uint32_t* a, const uint32_t* b){
    asm volatile(
        "mma.sync.aligned.m16n8k8.row.col.f32.tf32.tf32.f32 "
        "{%0,%1,%2,%3},{%4,%5,%6,%7},{%8,%9},{%0,%1,%2,%3};\n"
        : "+f"(d[0]), "+f"(d[1]), "+f"(d[2]), "+f"(d[3])
        : "r"(a[0]), "r"(a[1]), "r"(a[2]), "r"(a[3]), "r"(b[0]), "r"(b[1]));
}

// ---------------- gather node projections (float4, split arrays) ----------------
__global__ void k_xproj(const int* __restrict__ cidx,
                        const float* __restrict__ bz,
                        const float* __restrict__ br,
                        const float* __restrict__ bh)
{
    int i = blockIdx.x;
    int b = i / TT;
    const int* ci = cidx + (size_t)i*KC;
    int r0 = b*N_AT;
    const int grp = threadIdx.x >> 7;
    const int c4 = (threadIdx.x & 127) * 4;

    float4 a0, a1;
    if (grp == 0){
        a0 = *(const float4*)&bz[c4];
        a1 = *(const float4*)&br[c4];
    } else {
        a0 = *(const float4*)&bh[c4];
        a1 = make_float4(0.f,0.f,0.f,0.f);
    }
    const float* A0 = grp ? g_nodeH : g_nodeZ;
    const float* A1 = grp ? g_nodeS : g_nodeR;
    #pragma unroll
    for (int k=0;k<KC;k++){
        size_t row = (size_t)(r0 + ci[k])*HH + c4;
        float4 v0 = *(const float4*)&A0[row];
        float4 v1 = *(const float4*)&A1[row];
        a0.x+=v0.x; a0.y+=v0.y; a0.z+=v0.z; a0.w+=v0.w;
        a1.x+=v1.x; a1.y+=v1.y; a1.z+=v1.z; a1.w+=v1.w;
    }
    if (grp == 0){
        *(float4*)&g_Xz[(size_t)i*HH + c4] = a0;
        *(float4*)&g_Xr[(size_t)i*HH + c4] = a1;
    } else {
        *(float4*)&g_Xh[(size_t)i*HH + c4] = a0;
        *(float4*)&g_stopX[(size_t)i*HH + c4] = a1;
    }
}

__global__ void k_rootS(const int* __restrict__ rcidx)
{
    int b = blockIdx.x;
    const int* ci = rcidx + (size_t)b*KC;
    int c4 = threadIdx.x * 4;
    float4 ss = make_float4(0.f,0.f,0.f,0.f);
    #pragma unroll
    for (int k=0;k<KC;k++){
        float4 v = *(const float4*)&g_nodeS[(size_t)(b*N_AT + ci[k])*HH + c4];
        ss.x+=v.x; ss.y+=v.y; ss.z+=v.z; ss.w+=v.w;
    }
    *(float4*)&g_stopX[(size_t)(BT + b)*HH + c4] = ss;
}

__global__ void k_compact(const int* __restrict__ direction)
{
    int i = blockIdx.x*256 + threadIdx.x;
    if (i < BT && direction[i] == 1){
        int s = atomicAdd(&g_cnt, 1);
        g_list[s] = i;
    }
}

// ---------------- tf32 tensor-core GEMM ----------------
template<int EPI, bool NG, bool ZSEL, int GMODE>
__global__ void __launch_bounds__(256)
tgemm(const float* __restrict__ A, int lda,
      const float* __restrict__ Bm0, int ldb,
      const float* __restrict__ bias,
      float* __restrict__ C0, int ldc,
      int N, int K,
      const float* __restrict__ us,
      const float* __restrict__ xadd,
      const float* Bm1, const float* Bm2, const float* Bm3,
      float* C1, float* C2, float* C3)
{
    extern __shared__ float dynsm[];
    const int by = blockIdx.y, bx = blockIdx.x;
    const int rowb = by*128, colb = bx*128;
    if (GMODE){ if (rowb >= g_cnt) return; }

    const int tid  = threadIdx.x;
    const int warp = tid >> 5, lane = tid & 31;
    const int wm = warp & 3, wn = warp >> 2;
    const int gid = lane >> 2, tig = lane & 3;

    const float* Bm = Bm0;
    float* C = C0;
    if (ZSEL){
        if (blockIdx.z == 1){ Bm = Bm1; C = C1; }
        else if (blockIdx.z == 2){ Bm = Bm2; C = C2; }
        else if (blockIdx.z == 3){ Bm = Bm3; C = C3; }
    }

    uint32_t smem_base = (uint32_t)__cvta_generic_to_shared(dynsm);

    float acc[2][8][4];
    #pragma unroll
    for (int mt=0;mt<2;mt++)
        #pragma unroll
        for (int nt=0;nt<8;nt++)
            #pragma unroll
            for (int i=0;i<4;i++) acc[mt][nt][i]=0.f;

    const int nk = K >> 5;

    auto issue = [&](int kt, int stage){
        uint32_t sa = smem_base + stage*TG_STAGE*4;
        uint32_t sb = sa + TG_ABUF*4;
        #pragma unroll
        for (int i=0;i<4;i++){
            int q = tid + 256*i;
            int r = q >> 3, k4 = (q & 7)*4;
            size_t arow = (GMODE == 1) ? (size_t)g_list[rowb + r] : (size_t)(rowb + r);
            cp_async16(sa + (r*36 + k4)*4, A + arow*lda + kt*32 + k4);
        }
        #pragma unroll
        for (int i=0;i<4;i++){
            int q = tid + 256*i;
            int kr = q >> 5, n4 = (q & 31)*4;
            uint32_t dst = sb + (kr*132 + n4)*4;
            if (NG){
                int col = colb + n4;
                int bytes = (col + 3 < N) ? 16 : ((col < N) ? (N - col)*4 : 0);
                const float* src = Bm + (size_t)(kt*32 + kr)*ldb + (bytes ? col : 0);
                cp_async16z(dst, src, bytes);
            } else {
                cp_async16(dst, Bm + (size_t)(kt*32 + kr)*ldb + colb + n4);
            }
        }
        cp_commit();
    };

    issue(0, 0);
    if (nk > 1) issue(1, 1);

    for (int it=0; it<nk; it++){
        if (it+2 < nk) issue(it+2, (it+2)%3);
        if (it+1 < nk) cp_wait<1>(); else cp_wait<0>();
        __syncthreads();

        const uint32_t* As = (const uint32_t*)(dynsm + (it%3)*TG_STAGE);
        const uint32_t* Bs = (const uint32_t*)(dynsm + (it%3)*TG_STAGE + TG_ABUF);

        #pragma unroll
        for (int ks=0; ks<4; ks++){
            uint32_t af[2][4];
            #pragma unroll
            for (int mt=0; mt<2; mt++){
                int r = wm*32 + mt*16 + gid;
                af[mt][0] = As[r*36 + ks*8 + tig];
                af[mt][1] = As[(r+8)*36 + ks*8 + tig];
                af[mt][2] = As[r*36 + ks*8 + tig + 4];
                af[mt][3] = As[(r+8)*36 + ks*8 + tig + 4];
            }
            uint32_t bf[8][2];
            #pragma unroll
            for (int nt=0; nt<8; nt++){
                int n = wn*64 + nt*8 + gid;
                bf[nt][0] = Bs[(ks*8 + tig)*132 + n];
                bf[nt][1] = Bs[(ks*8 + tig + 4)*132 + n];
            }
            #pragma unroll
            for (int mt=0; mt<2; mt++)
                #pragma unroll
                for (int nt=0; nt<8; nt++)
                    mma_tf32(acc[mt][nt], af[mt], bf[nt]);
        }
        __syncthreads();
    }

    if (EPI == 2){
        #pragma unroll
        for (int mt=0; mt<2; mt++){
            int row0 = rowb + wm*32 + mt*16 + gid;
            float s0 = 0.f, s1 = 0.f;
            #pragma unroll
            for (int nt=0; nt<8; nt++){
                int col = colb + wn*64 + nt*8 + 2*tig;
                float b0 = bias[col], b1 = bias[col+1];
                float u0 = us[col],  u1 = us[col+1];
                float2 x0 = *(const float2*)&xadd[(size_t)row0*HH + col];
                float2 x1 = *(const float2*)&xadd[(size_t)(row0+8)*HH + col];
                float v;
                v = acc[mt][nt][0] + b0 + x0.x; s0 += (v>0.f? v:0.f)*u0;
                v = acc[mt][nt][1] + b1 + x0.y; s0 += (v>0.f? v:0.f)*u1;
                v = acc[mt][nt][2] + b0 + x1.x; s1 += (v>0.f? v:0.f)*u0;
                v = acc[mt][nt][3] + b1 + x1.y; s1 += (v>0.f? v:0.f)*u1;
            }
            s0 += __shfl_xor_sync(0xffffffffu, s0, 1);
            s0 += __shfl_xor_sync(0xffffffffu, s0, 2);
            s1 += __shfl_xor_sync(0xffffffffu, s1, 1);
            s1 += __shfl_xor_sync(0xffffffffu, s1, 2);
            if (tig == 0){
                atomicAdd(&g_score[row0], s0);
                atomicAdd(&g_score[row0+8], s1);
            }
        }
    } else {
        #pragma unroll
        for (int mt=0; mt<2; mt++){
            #pragma unroll
            for (int nt=0; nt<8; nt++){
                int col = colb + wn*64 + nt*8 + 2*tig;
                int row = rowb + wm*32 + mt*16 + gid;
                #pragma unroll
                for (int i=0; i<4; i++){
                    int cc = col + (i & 1);
                    int rr = row + ((i >> 1) ? 8 : 0);
                    if (!NG || cc < N){
                        float v = acc[mt][nt][i];
                        if (EPI != 3) v += bias[cc];
                        if (EPI == 1) v = v > 0.f ? v : 0.f;
                        C[(size_t)rr*ldc + cc] = v;
                    }
                }
            }
        }
    }
}

// ---------------- persistent scan kernel ----------------
__device__ __forceinline__ void gsync(int& epoch)
{
    __syncthreads();
    if (threadIdx.x == 0){
        __threadfence();
        atomicAdd(&g_bar, 1u);
        unsigned tgt = (unsigned)epoch * NBLK;
        while (*((volatile unsigned*)&g_bar) < tgt) { }
    }
    epoch++;
    __syncthreads();
}

__global__ void __launch_bounds__(256, 1)
k_scan(const int* __restrict__ nei_h,
       const float* __restrict__ Wzh,
       const float* __restrict__ Whh,
       const float* __restrict__ Ur)
{
    extern __shared__ float smem[];
    float4* WF  = (float4*)smem;
    float* ringf = smem + WF_FLOATS;

    const int tid = threadIdx.x;
    const int blk = blockIdx.x;
    const int rt = blk >> 4, ct = blk & 15;
    const int r0 = rt*64, c0 = ct*32;
    const int warp = tid >> 5, lane = tid & 31;
    const int wm = warp & 3, wn = warp >> 2;
    const int gid = lane >> 2, tig = lane & 3;
    const int id4a = tid*2, id4b = tid*2+1;
    const int sra = id4a >> 3, ska = (id4a & 7)*4;
    const int srb = id4b >> 3, skb = (id4b & 7)*4;
    const int ur_r = tid >> 3, ur_c = (tid & 7)*4;
    const int arow = tid >> 7;
    const int ac4  = (tid & 127) * 4;

    const uint32_t ring_u = (uint32_t)__cvta_generic_to_shared(ringf);

    for (int g = warp; g < 256; g += 8){
        int nt  = g & 1, wns = (g >> 1) & 1, ks = (g >> 2) & 3, chunk = g >> 4;
        int krow = chunk*32 + ks*8 + tig;
        int col  = c0 + wns*16 + nt*8 + gid;
        float4 v;
        v.x = Wzh[(size_t)krow*HH + col];
        v.y = Wzh[(size_t)(krow+4)*HH + col];
        v.z = Whh[(size_t)krow*HH + col];
        v.w = Whh[(size_t)(krow+4)*HH + col];
        WF[g*32 + lane] = v;
    }
    __syncthreads();

    int epoch = 1;

    for (int t = 0; t < TT; t++){
        // ---- phase A: gather sum_h, sum_g (float4, pair rows) ----
        #pragma unroll
        for (int pass=0; pass<2; pass++){
            int b = blk*4 + pass*2 + arow;
            const int* idx = nei_h + ((size_t)b*TT + t)*MAX_NB;
            const float* pr[8];
            #pragma unroll
            for (int n=0;n<8;n++) pr[n] = g_pair + (size_t)idx[n]*PW;
            float4 xr = *(const float4*)&g_Xr[((size_t)b*TT + t)*HH + ac4];
            float4 ah = make_float4(0.f,0.f,0.f,0.f);
            float4 ag = make_float4(0.f,0.f,0.f,0.f);
            #pragma unroll
            for (int n=0;n<8;n++){
                float4 hv = __ldcg((const float4*)(pr[n] + ac4));
                float4 uv = __ldcg((const float4*)(pr[n] + 512 + ac4));
                ah.x += hv.x; ah.y += hv.y; ah.z += hv.z; ah.w += hv.w;
                ag.x += hv.x * sigf(xr.x + uv.x);
                ag.y += hv.y * sigf(xr.y + uv.y);
                ag.z += hv.z * sigf(xr.z + uv.z);
                ag.w += hv.w * sigf(xr.w + uv.w);
            }
            *(float4*)&g_sumh[b*HH+ac4] = ah;
            *(float4*)&g_sumg[b*HH+ac4] = ag;
        }
        gsync(epoch);

        // ---- phase B: dual tf32 GEMM + GRU epilogue ----
        {
            float accz[2][4], acch[2][4];
            #pragma unroll
            for (int nt=0;nt<2;nt++)
                #pragma unroll
                for (int i=0;i<4;i++){ accz[nt][i]=0.f; acch[nt][i]=0.f; }

            auto issueB = [&](int chk){
                uint32_t sa = ring_u + (chk & 3)*RING_STAGE_B;
                cp_async16(sa + (sra*36+ska)*4, &g_sumh[(size_t)(r0+sra)*HH + chk*32 + ska]);
                cp_async16(sa + (srb*36+skb)*4, &g_sumh[(size_t)(r0+srb)*HH + chk*32 + skb]);
                cp_async16(sa + 9216 + (sra*36+ska)*4, &g_sumg[(size_t)(r0+sra)*HH + chk*32 + ska]);
                cp_async16(sa + 9216 + (srb*36+skb)*4, &g_sumg[(size_t)(r0+srb)*HH + chk*32 + skb]);
                cp_commit();
            };
            issueB(0); issueB(1); issueB(2);

            for (int chk=0; chk<16; chk++){
                if (chk < 14) cp_wait<2>(); else if (chk == 14) cp_wait<1>(); else cp_wait<0>();
                __syncthreads();
                if (chk+3 < 16) issueB(chk+3);

                const uint32_t* Ah = (const uint32_t*)(ringf + (chk & 3)*4608);
                const uint32_t* Ag = Ah + 2304;

                #pragma unroll
                for (int ks=0; ks<4; ks++){
                    int rb0 = wm*16 + gid;
                    uint32_t ah[4], ag[4];
                    ah[0]=Ah[rb0*36 + ks*8 + tig];     ah[1]=Ah[(rb0+8)*36 + ks*8 + tig];
                    ah[2]=Ah[rb0*36 + ks*8 + tig + 4]; ah[3]=Ah[(rb0+8)*36 + ks*8 + tig + 4];
                    ag[0]=Ag[rb0*36 + ks*8 + tig];     ag[1]=Ag[(rb0+8)*36 + ks*8 + tig];
                    ag[2]=Ag[rb0*36 + ks*8 + tig + 4]; ag[3]=Ag[(rb0+8)*36 + ks*8 + tig + 4];
                    #pragma unroll
                    for (int nt=0; nt<2; nt++){
                        int g = ((chk*4 + ks)*2 + wn)*2 + nt;
                        uint4 wf = *(const uint4*)&WF[g*32 + lane];
                        uint32_t bz[2] = {wf.x, wf.y};
                        uint32_t bh[2] = {wf.z, wf.w};
                        mma_tf32(accz[nt], ah, bz);
                        mma_tf32(acch[nt], ag, bh);
                    }
                }
            }

            #pragma unroll
            for (int nt=0; nt<2; nt++){
                #pragma unroll
                for (int half=0; half<2; half++){
                    int b   = r0 + wm*16 + gid + half*8;
                    int col = c0 + wn*16 + nt*8 + tig*2;
                    size_t xi = ((size_t)b*TT + t)*HH + col;
                    float2 xz = *(const float2*)&g_Xz[xi];
                    float2 xh = *(const float2*)&g_Xh[xi];
                    float2 sh = __ldcg((const float2*)&g_sumh[(size_t)b*HH + col]);
                    float z0 = sigf(xz.x + accz[nt][half*2+0]);
                    float z1 = sigf(xz.y + accz[nt][half*2+1]);
                    float p0 = tanhf(xh.x + acch[nt][half*2+0]);
                    float p1 = tanhf(xh.y + acch[nt][half*2+1]);
                    float2 out;
                    out.x = (1.f - z0)*sh.x + z0*p0;
                    out.y = (1.f - z1)*sh.y + z1*p1;
                    *(float2*)&g_pair[((size_t)b*TT + t + 1)*PW + col] = out;
                }
            }
        }
        gsync(epoch);

        if (t == TT-1) break;

        // ---- phase C: Uh(step-t rows) = new_h @ Ur ----
        {
            float accu[2][4];
            #pragma unroll
            for (int nt=0;nt<2;nt++)
                #pragma unroll
                for (int i=0;i<4;i++) accu[nt][i]=0.f;

            auto issueC = [&](int chk){
                uint32_t sa = ring_u + (chk & 3)*RING_STAGE_B;
                cp_async16(sa + (sra*36+ska)*4, &g_pair[((size_t)(r0+sra)*TT + t + 1)*PW + chk*32 + ska]);
                cp_async16(sa + (srb*36+skb)*4, &g_pair[((size_t)(r0+srb)*TT + t + 1)*PW + chk*32 + skb]);
                cp_async16(sa + 9216 + (ur_r*40 + ur_c)*4, &Ur[(size_t)(chk*32 + ur_r)*HH + c0 + ur_c]);
                cp_commit();
            };
            issueC(0); issueC(1); issueC(2);

            for (int chk=0; chk<16; chk++){
                if (chk < 14) cp_wait<2>(); else if (chk == 14) cp_wait<1>(); else cp_wait<0>();
                __syncthreads();
                if (chk+3 < 16) issueC(chk+3);

                const uint32_t* Ah = (const uint32_t*)(ringf + (chk & 3)*4608);
                const uint32_t* Uc = Ah + 2304;

                #pragma unroll
                for (int ks=0; ks<4; ks++){
                    int rb0 = wm*16 + gid;
                    uint32_t ah[4];
                    ah[0]=Ah[rb0*36 + ks*8 + tig];     ah[1]=Ah[(rb0+8)*36 + ks*8 + tig];
                    ah[2]=Ah[rb0*36 + ks*8 + tig + 4]; ah[3]=Ah[(rb0+8)*36 + ks*8 + tig + 4];
                    #pragma unroll
                    for (int nt=0; nt<2; nt++){
                        int n = wn*16 + nt*8 + gid;
                        uint32_t bu[2];
                        bu[0] = Uc[(ks*8 + tig)*40 + n];
                        bu[1] = Uc[(ks*8 + tig + 4)*40 + n];
                        mma_tf32(accu[nt], ah, bu);
                    }
                }
            }

            #pragma unroll
            for (int nt=0; nt<2; nt++){
                #pragma unroll
                for (int half=0; half<2; half++){
                    int b   = r0 + wm*16 + gid + half*8;
                    int col = c0 + wn*16 + nt*8 + tig*2;
                    float2 out;
                    out.x = accu[nt][half*2+0];
                    out.y = accu[nt][half*2+1];
                    *(float2*)&g_pair[((size_t)b*TT + t + 1)*PW + 512 + col] = out;
                }
            }
        }
        gsync(epoch);
    }
}

// ---------------- deferred o gather (float4: one 128-thread block per stop row) ----------------
__global__ void __launch_bounds__(128)
k_oall(const int* __restrict__ nei_o, const int* __restrict__ root_nei)
{
    int i = blockIdx.x;
    int c4 = threadIdx.x * 4;
    float4 o = make_float4(0.f,0.f,0.f,0.f);
    if (i < BT) {
        int tt = i % TT;
        const int* idx = nei_o + (size_t)i*MAX_NB;
        #pragma unroll
        for (int n=0;n<MAX_NB;n++){
            int id = idx[n];
            if (id > 0 && ((id-1) % TT) < tt){
                float4 v = __ldcg((const float4*)&g_pair[(size_t)id*PW + c4]);
                o.x+=v.x; o.y+=v.y; o.z+=v.z; o.w+=v.w;
            }
        }
    } else {
        int b = i - BT;
        const int* idx = root_nei + (size_t)b*MAX_NB;
        #pragma unroll
        for (int n=0;n<MAX_NB;n++){
            float4 v = __ldcg((const float4*)&g_pair[(size_t)idx[n]*PW + c4]);
            o.x+=v.x; o.y+=v.y; o.z+=v.z; o.w+=v.w;
        }
    }
    *(float4*)&g_stopO[(size_t)i*HH + c4] = o;
}

// ---------------- stop loss / acc ----------------
__global__ void k_stoploss(const int* __restrict__ direction, const float* __restrict__ usb)
{
    int i = blockIdx.x*256 + threadIdx.x;
    float li = 0.f, ci = 0.f;
    if (i < NSTOP){
        float s = g_score[i] + usb[0];
        float tgt = (i < BT) ? (float)direction[i] : 0.f;
        float sp = (s > 0.f) ? (s + log1pf(expf(-s))) : log1pf(expf(s));
        li = sp - s*tgt;
        float pred = (s >= 0.f) ? 1.f : 0.f;
        ci = (pred == tgt) ? 1.f : 0.f;
    }
    __shared__ float rl[256], rc[256];
    rl[threadIdx.x]=li; rc[threadIdx.x]=ci;
    __syncthreads();
    for (int st=128; st>0; st>>=1){
        if (threadIdx.x < st){ rl[threadIdx.x]+=rl[threadIdx.x+st]; rc[threadIdx.x]+=rc[threadIdx.x+st]; }
        __syncthreads();
    }
    if (threadIdx.x==0){
        atomicAdd(&g_red[3], rl[0]);
        atomicAdd(&g_red[4], rc[0]);
    }
}

// ---------------- pred head CE / acc over compacted rows ----------------
__global__ void k_ce(const int* __restrict__ target)
{
    int slot = blockIdx.x;
    if (slot >= g_cnt) return;
    int i = g_list[slot];
    int t = threadIdx.x;
    const float* S = g_predS + (size_t)slot*VV;
    float val[4];
    float lmax = -1e30f; int lidx = 0;
    #pragma unroll
    for (int r=0;r<4;r++){
        int v = t + 256*r;
        if (v < VV){
            float x = S[v];
            val[r] = x;
            if (x > lmax){ lmax = x; lidx = v; }
        } else val[r] = -1e30f;
    }
    __shared__ float smax[256]; __shared__ int sidx[256];
    smax[t]=lmax; sidx[t]=lidx;
    __syncthreads();
    for (int st=128; st>0; st>>=1){
        if (t < st){
            float o = smax[t+st]; int oi = sidx[t+st];
            if (o > smax[t] || (o == smax[t] && oi < sidx[t])){ smax[t]=o; sidx[t]=oi; }
        }
        __syncthreads();
    }
    float m = smax[0]; int am = sidx[0];
    __syncthreads();
    float se = 0.f;
    #pragma unroll
    for (int r=0;r<4;r++){
        int v = t + 256*r;
        if (v < VV) se += expf(val[r] - m);
    }
    __shared__ float ssum[256];
    ssum[t]=se;
    __syncthreads();
    for (int st=128; st>0; st>>=1){
        if (t < st) ssum[t]+=ssum[t+st];
        __syncthreads();
    }
    if (t==0){
        float lse = m + logf(ssum[0]);
        int tg = target[i];
        float ce = lse - S[tg];
        atomicAdd(&g_red[0], ce);
        atomicAdd(&g_red[1], (am==tg) ? 1.f : 0.f);
        atomicAdd(&g_red[2], 1.f);
    }
}

__global__ void k_final(float* out)
{
    out[0] = g_red[0] / (float)BB;
    out[1] = g_red[3] / (float)BB;
    out[2] = g_red[1] / g_red[2];
    out[3] = g_red[4] / (float)NSTOP;
}

// ---------------- host launch ----------------
extern "C" void kernel_launch(void* const* d_in, const int* in_sizes, int n_in,
                              void* d_out, int out_size)
{
    const float* node_rep = (const float*)d_in[0];
    const int*   clique   = (const int*)  d_in[1];
    const int*   rclique  = (const int*)  d_in[2];
    const int*   nei_h    = (const int*)  d_in[3];
    const int*   nei_o    = (const int*)  d_in[4];
    const int*   rnei     = (const int*)  d_in[5];
    const int*   dir      = (const int*)  d_in[6];
    const int*   ptgt     = (const int*)  d_in[7];
    const float* Wz  = (const float*)d_in[8];
    const float* Wzb = (const float*)d_in[9];
    const float* Wr  = (const float*)d_in[10];
    const float* Wrb = (const float*)d_in[11];
    const float* Ur  = (const float*)d_in[12];
    const float* Wh  = (const float*)d_in[13];
    const float* Whb = (const float*)d_in[14];
    const float* Ww  = (const float*)d_in[15];
    const float* Wwb = (const float*)d_in[16];
    const float* Uw  = (const float*)d_in[17];
    const float* Ub  = (const float*)d_in[18];
    const float* Wo  = (const float*)d_in[19];
    const float* Wob = (const float*)d_in[20];
    const float* Us  = (const float*)d_in[21];
    const float* Usb = (const float*)d_in[22];

    float *pair, *nZ, *nR, *nH, *nS, *stopO, *stopX, *predH, *predS, *score, *red;
    unsigned* bar; int* cnt; int* list;
    cudaGetSymbolAddress((void**)&pair,  g_pair);
    cudaGetSymbolAddress((void**)&nZ,    g_nodeZ);
    cudaGetSymbolAddress((void**)&nR,    g_nodeR);
    cudaGetSymbolAddress((void**)&nH,    g_nodeH);
    cudaGetSymbolAddress((void**)&nS,    g_nodeS);
    cudaGetSymbolAddress((void**)&stopO, g_stopO);
    cudaGetSymbolAddress((void**)&stopX, g_stopX);
    cudaGetSymbolAddress((void**)&predH, g_predH);
    cudaGetSymbolAddress((void**)&predS, g_predS);
    cudaGetSymbolAddress((void**)&score, g_score);
    cudaGetSymbolAddress((void**)&red,   g_red);
    cudaGetSymbolAddress((void**)&bar,   g_bar);
    cudaGetSymbolAddress((void**)&cnt,   g_cnt);
    cudaGetSymbolAddress((void**)&list,  g_list);

    static int attr_set = 0;
    if (!attr_set){
        cudaFuncSetAttribute(k_scan, cudaFuncAttributeMaxDynamicSharedMemorySize, SMEM_SCAN);
        cudaFuncSetAttribute(tgemm<3,false,true,0>,  cudaFuncAttributeMaxDynamicSharedMemorySize, SMEM_TG);
        cudaFuncSetAttribute(tgemm<2,false,false,0>, cudaFuncAttributeMaxDynamicSharedMemorySize, SMEM_TG);
        cudaFuncSetAttribute(tgemm<1,false,false,1>, cudaFuncAttributeMaxDynamicSharedMemorySize, SMEM_TG);
        cudaFuncSetAttribute(tgemm<0,true,false,2>,  cudaFuncAttributeMaxDynamicSharedMemorySize, SMEM_TG);
        attr_set = 1;
    }

    cudaMemsetAsync(pair, 0, sizeof(float)*(size_t)NMSG*PW);
    cudaMemsetAsync(score,0, sizeof(float)*NSTOP);
    cudaMemsetAsync(red,  0, sizeof(float)*8);
    cudaMemsetAsync(bar,  0, sizeof(unsigned));
    cudaMemsetAsync(cnt,  0, sizeof(int));

    // node-level projections (Wz_x, Wr, Wh_x, Uw_x) in one launch
    dim3 gN(4, (BB*N_AT)/128, 4);
    tgemm<3,false,true,0><<<gN, 256, SMEM_TG>>>(node_rep, HH, Wz, HH, nullptr, nZ, HH,
                                                HH, HH, nullptr, nullptr,
                                                Wr, Wh, Uw, nR, nH, nS);
    k_xproj<<<BT, 256>>>(clique, Wzb, Wrb, Whb);
    k_rootS<<<BB, 128>>>(rclique);
    k_compact<<<BT/256, 256>>>(dir);

    // sequential scan
    const float* Wzh = Wz + (size_t)HH*HH;
    const float* Whh = Wh + (size_t)HH*HH;
    k_scan<<<NBLK, 256, SMEM_SCAN>>>(nei_h, Wzh, Whh, Ur);

    // stop head
    k_oall<<<NSTOP, 128>>>(nei_o, rnei);
    tgemm<2,false,false,0><<<dim3(4, NSTOP/128), 256, SMEM_TG>>>(stopO, HH,
        Uw + (size_t)HH*HH, HH, Ub, nullptr, 0, HH, HH, Us, stopX,
        nullptr, nullptr, nullptr, nullptr, nullptr, nullptr);
    k_stoploss<<<NSTOP/256, 256>>>(dir, Usb);

    // pred head over compacted rows
    tgemm<1,false,false,1><<<dim3(4, BT/128), 256, SMEM_TG>>>(pair + PW, PW, Ww, HH, Wwb,
        predH, HH, HH, HH, nullptr, nullptr,
        nullptr, nullptr, nullptr, nullptr, nullptr, nullptr);
    tgemm<0,true,false,2><<<dim3(7, BT/128), 256, SMEM_TG>>>(predH, HH, Wo, VV, Wob,
        predS, VV, VV, HH, nullptr, nullptr,
        nullptr, nullptr, nullptr, nullptr, nullptr, nullptr);
    k_ce<<<BT, 256>>>(ptgt);

    k_final<<<1,1>>>((float*)d_out);
}

// round 17
// speedup vs baseline: 2.3300x; 1.3497x over previous
#include <cuda_runtime.h>
#include <cuda_bf16.h>
#include <math.h>
#include <stdint.h>

#define BB 512
#define TT 64
#define HH 512
#define VV 780
#define N_AT 40
#define KC 4
#define MAX_NB 8
#define NMSG (BB*TT+1)
#define BT (BB*TT)
#define NSTOP (BT+BB)
#define H2 (2*HH)
#define NBLK 128
#define PW 1024   // pair row width in bf16: [h(512) | Uh(512)]

// k_scan smem: packed bf16 weight fragments (64KB) + 4-stage ring (40KB)
#define WF_BYTES 65536
#define RING_STAGE 10240
#define SMEM_SCAN (WF_BYTES + 4*RING_STAGE)   // 106496 B

// tgemm: 3-stage ring of (A[128][36] + B[32][132]) fp32 tiles
#define TG_ABUF (128*36)
#define TG_BBUF (32*132)
#define TG_STAGE (TG_ABUF + TG_BBUF)
#define SMEM_TG (3*TG_STAGE*4)

// ---------------- device scratch ----------------
__device__ __nv_bfloat16 g_pairh[(size_t)NMSG*PW];   // message table, bf16
__device__ __nv_bfloat16 g_sumhb[BB*HH];
__device__ __nv_bfloat16 g_sumgb[BB*HH];
__device__ __nv_bfloat16 g_UrT  [HH*HH];             // Ur transposed, bf16
__device__ float g_sumh  [BB*HH];                    // fp32 copy for epilogue
__device__ float g_hfp   [BT*HH];                    // fp32 h for pred head
__device__ float g_nodeZ [BB*N_AT*HH];
__device__ float g_nodeR [BB*N_AT*HH];
__device__ float g_nodeH [BB*N_AT*HH];
__device__ float g_nodeS [BB*N_AT*HH];
__device__ float g_Xz    [BT*HH];
__device__ float g_Xr    [BT*HH];
__device__ float g_Xh    [BT*HH];
__device__ float g_stopO [NSTOP*HH];
__device__ float g_stopX [NSTOP*HH];
__device__ float g_predH [BT*HH];
__device__ float g_predS [BT*VV];
__device__ float g_score [NSTOP];
__device__ float g_red   [8];
__device__ unsigned g_bar;
__device__ int g_cnt;
__device__ int g_list[BT];

__device__ __forceinline__ float sigf(float x){ return 1.f/(1.f+expf(-x)); }

__device__ __forceinline__ void cp_async16(uint32_t dst, const void* src){
    asm volatile("cp.async.cg.shared.global [%0], [%1], 16;\n" :: "r"(dst), "l"(src));
}
__device__ __forceinline__ void cp_async16z(uint32_t dst, const void* src, int bytes){
    asm volatile("cp.async.cg.shared.global [%0], [%1], 16, %2;\n" :: "r"(dst), "l"(src), "r"(bytes));
}
__device__ __forceinline__ void cp_commit(){ asm volatile("cp.async.commit_group;\n"); }
template<int N> __device__ __forceinline__ void cp_wait(){ asm volatile("cp.async.wait_group %0;\n" :: "n"(N)); }

__device__ __forceinline__ void mma_tf32(float* d, const uint32_t* a, const uint32_t* b){
    asm volatile(
        "mma.sync.aligned.m16n8k8.row.col.f32.tf32.tf32.f32 "
        "{%0,%1,%2,%3},{%4,%5,%6,%7},{%8,%9},{%0,%1,%2,%3};\n"
        : "+f"(d[0]), "+f"(d[1]), "+f"(d[2]), "+f"(d[3])
        : "r"(a[0]), "r"(a[1]), "r"(a[2]), "r"(a[3]), "r"(b[0]), "r"(b[1]));
}
__device__ __forceinline__ void mma_bf16(float* d, const uint32_t* a, uint32_t b0, uint32_t b1){
    asm volatile(
        "mma.sync.aligned.m16n8k16.row.col.f32.bf16.bf16.f32 "
        "{%0,%1,%2,%3},{%4,%5,%6,%7},{%8,%9},{%0,%1,%2,%3};\n"
        : "+f"(d[0]), "+f"(d[1]), "+f"(d[2]), "+f"(d[3])
        : "r"(a[0]), "r"(a[1]), "r"(a[2]), "r"(a[3]), "r"(b0), "r"(b1));
}
__device__ __forceinline__ uint32_t packbf(float lo, float hi){
    __nv_bfloat162 v = __floats2bfloat162_rn(lo, hi);
    return *(uint32_t*)&v;
}

// ---------------- Ur transpose + convert to bf16 ----------------
__global__ void k_prep(const float* __restrict__ Ur)
{
    __shared__ float tile[32][33];
    int k0 = blockIdx.y*32, n0 = blockIdx.x*32;
    int tx = threadIdx.x & 31, ty = threadIdx.x >> 5;
    #pragma unroll
    for (int r=ty; r<32; r+=8) tile[r][tx] = Ur[(size_t)(k0+r)*HH + n0+tx];
    __syncthreads();
    #pragma unroll
    for (int r=ty; r<32; r+=8)
        g_UrT[(size_t)(n0+r)*HH + k0+tx] = __float2bfloat16(tile[tx][r]);
}

// ---------------- gather node projections (float4, split arrays) ----------------
__global__ void k_xproj(const int* __restrict__ cidx,
                        const float* __restrict__ bz,
                        const float* __restrict__ br,
                        const float* __restrict__ bh)
{
    int i = blockIdx.x;
    int b = i / TT;
    const int* ci = cidx + (size_t)i*KC;
    int r0 = b*N_AT;
    const int grp = threadIdx.x >> 7;
    const int c4 = (threadIdx.x & 127) * 4;

    float4 a0, a1;
    if (grp == 0){
        a0 = *(const float4*)&bz[c4];
        a1 = *(const float4*)&br[c4];
    } else {
        a0 = *(const float4*)&bh[c4];
        a1 = make_float4(0.f,0.f,0.f,0.f);
    }
    const float* A0 = grp ? g_nodeH : g_nodeZ;
    const float* A1 = grp ? g_nodeS : g_nodeR;
    #pragma unroll
    for (int k=0;k<KC;k++){
        size_t row = (size_t)(r0 + ci[k])*HH + c4;
        float4 v0 = *(const float4*)&A0[row];
        float4 v1 = *(const float4*)&A1[row];
        a0.x+=v0.x; a0.y+=v0.y; a0.z+=v0.z; a0.w+=v0.w;
        a1.x+=v1.x; a1.y+=v1.y; a1.z+=v1.z; a1.w+=v1.w;
    }
    if (grp == 0){
        *(float4*)&g_Xz[(size_t)i*HH + c4] = a0;
        *(float4*)&g_Xr[(size_t)i*HH + c4] = a1;
    } else {
        *(float4*)&g_Xh[(size_t)i*HH + c4] = a0;
        *(float4*)&g_stopX[(size_t)i*HH + c4] = a1;
    }
}

__global__ void k_rootS(const int* __restrict__ rcidx)
{
    int b = blockIdx.x;
    const int* ci = rcidx + (size_t)b*KC;
    int c4 = threadIdx.x * 4;
    float4 ss = make_float4(0.f,0.f,0.f,0.f);
    #pragma unroll
    for (int k=0;k<KC;k++){
        float4 v = *(const float4*)&g_nodeS[(size_t)(b*N_AT + ci[k])*HH + c4];
        ss.x+=v.x; ss.y+=v.y; ss.z+=v.z; ss.w+=v.w;
    }
    *(float4*)&g_stopX[(size_t)(BT + b)*HH + c4] = ss;
}

__global__ void k_compact(const int* __restrict__ direction)
{
    int i = blockIdx.x*256 + threadIdx.x;
    if (i < BT && direction[i] == 1){
        int s = atomicAdd(&g_cnt, 1);
        g_list[s] = i;
    }
}

// ---------------- tf32 tensor-core GEMM (heads; unchanged) ----------------
template<int EPI, bool NG, bool ZSEL, int GMODE>
__global__ void __launch_bounds__(256)
tgemm(const float* __restrict__ A, int lda,
      const float* __restrict__ Bm0, int ldb,
      const float* __restrict__ bias,
      float* __restrict__ C0, int ldc,
      int N, int K,
      const float* __restrict__ us,
      const float* __restrict__ xadd,
      const float* Bm1, const float* Bm2, const float* Bm3,
      float* C1, float* C2, float* C3)
{
    extern __shared__ float dynsm[];
    const int by = blockIdx.y, bx = blockIdx.x;
    const int rowb = by*128, colb = bx*128;
    if (GMODE){ if (rowb >= g_cnt) return; }

    const int tid  = threadIdx.x;
    const int warp = tid >> 5, lane = tid & 31;
    const int wm = warp & 3, wn = warp >> 2;
    const int gid = lane >> 2, tig = lane & 3;

    const float* Bm = Bm0;
    float* C = C0;
    if (ZSEL){
        if (blockIdx.z == 1){ Bm = Bm1; C = C1; }
        else if (blockIdx.z == 2){ Bm = Bm2; C = C2; }
        else if (blockIdx.z == 3){ Bm = Bm3; C = C3; }
    }

    uint32_t smem_base = (uint32_t)__cvta_generic_to_shared(dynsm);

    float acc[2][8][4];
    #pragma unroll
    for (int mt=0;mt<2;mt++)
        #pragma unroll
        for (int nt=0;nt<8;nt++)
            #pragma unroll
            for (int i=0;i<4;i++) acc[mt][nt][i]=0.f;

    const int nk = K >> 5;

    auto issue = [&](int kt, int stage){
        uint32_t sa = smem_base + stage*TG_STAGE*4;
        uint32_t sb = sa + TG_ABUF*4;
        #pragma unroll
        for (int i=0;i<4;i++){
            int q = tid + 256*i;
            int r = q >> 3, k4 = (q & 7)*4;
            size_t arow = (GMODE == 1) ? (size_t)g_list[rowb + r] : (size_t)(rowb + r);
            cp_async16(sa + (r*36 + k4)*4, A + arow*lda + kt*32 + k4);
        }
        #pragma unroll
        for (int i=0;i<4;i++){
            int q = tid + 256*i;
            int kr = q >> 5, n4 = (q & 31)*4;
            uint32_t dst = sb + (kr*132 + n4)*4;
            if (NG){
                int col = colb + n4;
                int bytes = (col + 3 < N) ? 16 : ((col < N) ? (N - col)*4 : 0);
                const float* src = Bm + (size_t)(kt*32 + kr)*ldb + (bytes ? col : 0);
                cp_async16z(dst, src, bytes);
            } else {
                cp_async16(dst, Bm + (size_t)(kt*32 + kr)*ldb + colb + n4);
            }
        }
        cp_commit();
    };

    issue(0, 0);
    if (nk > 1) issue(1, 1);

    for (int it=0; it<nk; it++){
        if (it+2 < nk) issue(it+2, (it+2)%3);
        if (it+1 < nk) cp_wait<1>(); else cp_wait<0>();
        __syncthreads();

        const uint32_t* As = (const uint32_t*)(dynsm + (it%3)*TG_STAGE);
        const uint32_t* Bs = (const uint32_t*)(dynsm + (it%3)*TG_STAGE + TG_ABUF);

        #pragma unroll
        for (int ks=0; ks<4; ks++){
            uint32_t af[2][4];
            #pragma unroll
            for (int mt=0; mt<2; mt++){
                int r = wm*32 + mt*16 + gid;
                af[mt][0] = As[r*36 + ks*8 + tig];
                af[mt][1] = As[(r+8)*36 + ks*8 + tig];
                af[mt][2] = As[r*36 + ks*8 + tig + 4];
                af[mt][3] = As[(r+8)*36 + ks*8 + tig + 4];
            }
            uint32_t bf[8][2];
            #pragma unroll
            for (int nt=0; nt<8; nt++){
                int n = wn*64 + nt*8 + gid;
                bf[nt][0] = Bs[(ks*8 + tig)*132 + n];
                bf[nt][1] = Bs[(ks*8 + tig + 4)*132 + n];
            }
            #pragma unroll
            for (int mt=0; mt<2; mt++)
                #pragma unroll
                for (int nt=0; nt<8; nt++)
                    mma_tf32(acc[mt][nt], af[mt], bf[nt]);
        }
        __syncthreads();
    }

    if (EPI == 2){
        #pragma unroll
        for (int mt=0; mt<2; mt++){
            int row0 = rowb + wm*32 + mt*16 + gid;
            float s0 = 0.f, s1 = 0.f;
            #pragma unroll
            for (int nt=0; nt<8; nt++){
                int col = colb + wn*64 + nt*8 + 2*tig;
                float b0 = bias[col], b1 = bias[col+1];
                float u0 = us[col],  u1 = us[col+1];
                float2 x0 = *(const float2*)&xadd[(size_t)row0*HH + col];
                float2 x1 = *(const float2*)&xadd[(size_t)(row0+8)*HH + col];
                float v;
                v = acc[mt][nt][0] + b0 + x0.x; s0 += (v>0.f? v:0.f)*u0;
                v = acc[mt][nt][1] + b1 + x0.y; s0 += (v>0.f? v:0.f)*u1;
                v = acc[mt][nt][2] + b0 + x1.x; s1 += (v>0.f? v:0.f)*u0;
                v = acc[mt][nt][3] + b1 + x1.y; s1 += (v>0.f? v:0.f)*u1;
            }
            s0 += __shfl_xor_sync(0xffffffffu, s0, 1);
            s0 += __shfl_xor_sync(0xffffffffu, s0, 2);
            s1 += __shfl_xor_sync(0xffffffffu, s1, 1);
            s1 += __shfl_xor_sync(0xffffffffu, s1, 2);
            if (tig == 0){
                atomicAdd(&g_score[row0], s0);
                atomicAdd(&g_score[row0+8], s1);
            }
        }
    } else {
        #pragma unroll
        for (int mt=0; mt<2; mt++){
            #pragma unroll
            for (int nt=0; nt<8; nt++){
                int col = colb + wn*64 + nt*8 + 2*tig;
                int row = rowb + wm*32 + mt*16 + gid;
                #pragma unroll
                for (int i=0; i<4; i++){
                    int cc = col + (i & 1);
                    int rr = row + ((i >> 1) ? 8 : 0);
                    if (!NG || cc < N){
                        float v = acc[mt][nt][i];
                        if (EPI != 3) v += bias[cc];
                        if (EPI == 1) v = v > 0.f ? v : 0.f;
                        C[(size_t)rr*ldc + cc] = v;
                    }
                }
            }
        }
    }
}

// ---------------- persistent scan kernel (bf16 data path) ----------------
__device__ __forceinline__ void gsync(int& epoch)
{
    __syncthreads();
    if (threadIdx.x == 0){
        __threadfence();
        atomicAdd(&g_bar, 1u);
        unsigned tgt = (unsigned)epoch * NBLK;
        while (*((volatile unsigned*)&g_bar) < tgt) { }
    }
    epoch++;
    __syncthreads();
}

__global__ void __launch_bounds__(256, 1)
k_scan(const int* __restrict__ nei_h,
       const float* __restrict__ Wzh,
       const float* __restrict__ Whh)
{
    extern __shared__ char smem[];
    uint4* WF   = (uint4*)smem;                  // 128 groups x 32 lanes, bf16-packed
    char* ringb = smem + WF_BYTES;               // 4 stages x 10240B

    const int tid = threadIdx.x;
    const int blk = blockIdx.x;
    const int rt = blk >> 4, ct = blk & 15;
    const int r0 = rt*64, c0 = ct*32;
    const int warp = tid >> 5, lane = tid & 31;
    const int wm = warp & 3, wn = warp >> 2;
    const int gid = lane >> 2, tig = lane & 3;
    // cp.async mappings (A-tiles 64x32 bf16, stride 40 bf16)
    const int qa_row = tid >> 2, qa_c8 = (tid & 3)*8;
    const int qu_n   = (tid & 127) >> 2, qu_k8 = (tid & 3)*8;
    // phase A: 4 b's, 64 threads each, 8 cols/thread
    const int bsel = tid >> 6;
    const int ac8  = (tid & 63) * 8;

    const uint32_t ring_u = (uint32_t)__cvta_generic_to_shared(ringb);

    // pack Wz/Wh fragments (bf16): group g = ((chunk*2+kk)*2+wns)*2+nt
    for (int g = warp; g < 128; g += 8){
        int nt = g & 1, wns = (g >> 1) & 1, kk = (g >> 2) & 1, chunk = g >> 3;
        int k = chunk*32 + kk*16 + 2*tig;
        int col = c0 + wns*16 + nt*8 + gid;
        uint4 v;
        v.x = packbf(Wzh[(size_t)k*HH+col],     Wzh[(size_t)(k+1)*HH+col]);
        v.y = packbf(Wzh[(size_t)(k+8)*HH+col], Wzh[(size_t)(k+9)*HH+col]);
        v.z = packbf(Whh[(size_t)k*HH+col],     Whh[(size_t)(k+1)*HH+col]);
        v.w = packbf(Whh[(size_t)(k+8)*HH+col], Whh[(size_t)(k+9)*HH+col]);
        WF[g*32 + lane] = v;
    }
    __syncthreads();

    int epoch = 1;

    for (int t = 0; t < TT; t++){
        // ---- phase A: gather sum_h, sum_g (bf16 pair rows, 16B loads) ----
        {
            int b = blk*4 + bsel;
            const int* idx = nei_h + ((size_t)b*TT + t)*MAX_NB;
            int ii[8];
            #pragma unroll
            for (int n=0;n<8;n++) ii[n] = idx[n];
            float4 x0 = *(const float4*)&g_Xr[((size_t)b*TT + t)*HH + ac8];
            float4 x1 = *(const float4*)&g_Xr[((size_t)b*TT + t)*HH + ac8 + 4];
            float xr[8] = {x0.x,x0.y,x0.z,x0.w,x1.x,x1.y,x1.z,x1.w};
            float ah[8], ag[8];
            #pragma unroll
            for (int j=0;j<8;j++){ ah[j]=0.f; ag[j]=0.f; }
            #pragma unroll
            for (int n=0;n<8;n++){
                const __nv_bfloat16* p = g_pairh + (size_t)ii[n]*PW;
                uint4 hr = __ldcg((const uint4*)(p + ac8));
                uint4 ur = __ldcg((const uint4*)(p + 512 + ac8));
                const __nv_bfloat162* h2 = (const __nv_bfloat162*)&hr;
                const __nv_bfloat162* u2 = (const __nv_bfloat162*)&ur;
                #pragma unroll
                for (int j=0;j<4;j++){
                    float2 hf = __bfloat1622float2(h2[j]);
                    float2 uf = __bfloat1622float2(u2[j]);
                    ah[2*j]   += hf.x; ah[2*j+1] += hf.y;
                    ag[2*j]   += hf.x * sigf(xr[2*j]   + uf.x);
                    ag[2*j+1] += hf.y * sigf(xr[2*j+1] + uf.y);
                }
            }
            size_t so = (size_t)b*HH + ac8;
            *(float4*)&g_sumh[so]   = make_float4(ah[0],ah[1],ah[2],ah[3]);
            *(float4*)&g_sumh[so+4] = make_float4(ah[4],ah[5],ah[6],ah[7]);
            uint4 hb, gb;
            hb.x = packbf(ah[0],ah[1]); hb.y = packbf(ah[2],ah[3]);
            hb.z = packbf(ah[4],ah[5]); hb.w = packbf(ah[6],ah[7]);
            gb.x = packbf(ag[0],ag[1]); gb.y = packbf(ag[2],ag[3]);
            gb.z = packbf(ag[4],ag[5]); gb.w = packbf(ag[6],ag[7]);
            *(uint4*)&g_sumhb[so] = hb;
            *(uint4*)&g_sumgb[so] = gb;
        }
        gsync(epoch);

        // ---- phase B: dual bf16 GEMM + GRU epilogue ----
        {
            float accz[2][4], acch[2][4];
            #pragma unroll
            for (int nt=0;nt<2;nt++)
                #pragma unroll
                for (int i=0;i<4;i++){ accz[nt][i]=0.f; acch[nt][i]=0.f; }

            auto issueB = [&](int chk){
                uint32_t sa = ring_u + (chk & 3)*RING_STAGE;
                uint32_t off = qa_row*80 + qa_c8*2;
                cp_async16(sa + off,        g_sumhb + (size_t)(r0+qa_row)*HH + chk*32 + qa_c8);
                cp_async16(sa + 5120 + off, g_sumgb + (size_t)(r0+qa_row)*HH + chk*32 + qa_c8);
                cp_commit();
            };
            issueB(0); issueB(1); issueB(2);

            for (int chk=0; chk<16; chk++){
                if (chk < 14) cp_wait<2>(); else if (chk == 14) cp_wait<1>(); else cp_wait<0>();
                __syncthreads();
                if (chk+3 < 16) issueB(chk+3);

                const uint32_t* AhW = (const uint32_t*)(ringb + (chk & 3)*RING_STAGE);
                const uint32_t* AgW = AhW + 1280;

                #pragma unroll
                for (int kk=0; kk<2; kk++){
                    int rb0 = wm*16 + gid;
                    uint32_t ah[4], ag[4];
                    ah[0]=AhW[rb0*20 + kk*8 + tig];     ah[1]=AhW[(rb0+8)*20 + kk*8 + tig];
                    ah[2]=AhW[rb0*20 + kk*8 + tig + 4]; ah[3]=AhW[(rb0+8)*20 + kk*8 + tig + 4];
                    ag[0]=AgW[rb0*20 + kk*8 + tig];     ag[1]=AgW[(rb0+8)*20 + kk*8 + tig];
                    ag[2]=AgW[rb0*20 + kk*8 + tig + 4]; ag[3]=AgW[(rb0+8)*20 + kk*8 + tig + 4];
                    #pragma unroll
                    for (int nt=0; nt<2; nt++){
                        uint4 wf = WF[((((chk*2 + kk)*2 + wn)*2) + nt)*32 + lane];
                        mma_bf16(accz[nt], ah, wf.x, wf.y);
                        mma_bf16(acch[nt], ag, wf.z, wf.w);
                    }
                }
            }

            #pragma unroll
            for (int nt=0; nt<2; nt++){
                #pragma unroll
                for (int half=0; half<2; half++){
                    int b   = r0 + wm*16 + gid + half*8;
                    int col = c0 + wn*16 + nt*8 + tig*2;
                    size_t xi = ((size_t)b*TT + t)*HH + col;
                    float2 xz = *(const float2*)&g_Xz[xi];
                    float2 xh = *(const float2*)&g_Xh[xi];
                    float2 sh = __ldcg((const float2*)&g_sumh[(size_t)b*HH + col]);
                    float z0 = sigf(xz.x + accz[nt][half*2+0]);
                    float z1 = sigf(xz.y + accz[nt][half*2+1]);
                    float p0 = tanhf(xh.x + acch[nt][half*2+0]);
                    float p1 = tanhf(xh.y + acch[nt][half*2+1]);
                    float o0 = (1.f - z0)*sh.x + z0*p0;
                    float o1 = (1.f - z1)*sh.y + z1*p1;
                    *(uint32_t*)&g_pairh[((size_t)b*TT + t + 1)*PW + col] = packbf(o0, o1);
                    float2 of; of.x = o0; of.y = o1;
                    *(float2*)&g_hfp[xi] = of;
                }
            }
        }
        gsync(epoch);

        if (t == TT-1) break;

        // ---- phase C: Uh(step-t rows) = new_h @ Ur (bf16) ----
        {
            float accu[2][4];
            #pragma unroll
            for (int nt=0;nt<2;nt++)
                #pragma unroll
                for (int i=0;i<4;i++) accu[nt][i]=0.f;

            auto issueC = [&](int chk){
                uint32_t sa = ring_u + (chk & 3)*RING_STAGE;
                cp_async16(sa + qa_row*80 + qa_c8*2,
                           g_pairh + ((size_t)(r0+qa_row)*TT + t + 1)*PW + chk*32 + qa_c8);
                if (tid < 128)
                    cp_async16(sa + 5120 + qu_n*80 + qu_k8*2,
                               g_UrT + (size_t)(c0+qu_n)*HH + chk*32 + qu_k8);
                cp_commit();
            };
            issueC(0); issueC(1); issueC(2);

            for (int chk=0; chk<16; chk++){
                if (chk < 14) cp_wait<2>(); else if (chk == 14) cp_wait<1>(); else cp_wait<0>();
                __syncthreads();
                if (chk+3 < 16) issueC(chk+3);

                const uint32_t* AhW = (const uint32_t*)(ringb + (chk & 3)*RING_STAGE);
                const uint32_t* UcW = AhW + 1280;

                #pragma unroll
                for (int kk=0; kk<2; kk++){
                    int rb0 = wm*16 + gid;
                    uint32_t ah[4];
                    ah[0]=AhW[rb0*20 + kk*8 + tig];     ah[1]=AhW[(rb0+8)*20 + kk*8 + tig];
                    ah[2]=AhW[rb0*20 + kk*8 + tig + 4]; ah[3]=AhW[(rb0+8)*20 + kk*8 + tig + 4];
                    #pragma unroll
                    for (int nt=0; nt<2; nt++){
                        int nl = wn*16 + nt*8 + gid;
                        uint32_t b0 = UcW[nl*20 + kk*8 + tig];
                        uint32_t b1 = UcW[nl*20 + kk*8 + tig + 4];
                        mma_bf16(accu[nt], ah, b0, b1);
                    }
                }
            }

            #pragma unroll
            for (int nt=0; nt<2; nt++){
                #pragma unroll
                for (int half=0; half<2; half++){
                    int b   = r0 + wm*16 + gid + half*8;
                    int col = c0 + wn*16 + nt*8 + tig*2;
                    *(uint32_t*)&g_pairh[((size_t)b*TT + t + 1)*PW + 512 + col] =
                        packbf(accu[nt][half*2+0], accu[nt][half*2+1]);
                }
            }
        }
        gsync(epoch);
    }
}

// ---------------- deferred o gather (bf16 pair rows, 64 thr/row) ----------------
__global__ void __launch_bounds__(64)
k_oall(const int* __restrict__ nei_o, const int* __restrict__ root_nei)
{
    int i = blockIdx.x;
    int c8 = threadIdx.x * 8;
    float o[8];
    #pragma unroll
    for (int j=0;j<8;j++) o[j]=0.f;
    if (i < BT) {
        int tt = i % TT;
        const int* idx = nei_o + (size_t)i*MAX_NB;
        #pragma unroll
        for (int n=0;n<MAX_NB;n++){
            int id = idx[n];
            if (id > 0 && ((id-1) % TT) < tt){
                uint4 hr = __ldcg((const uint4*)(g_pairh + (size_t)id*PW + c8));
                const __nv_bfloat162* h2 = (const __nv_bfloat162*)&hr;
                #pragma unroll
                for (int j=0;j<4;j++){
                    float2 hf = __bfloat1622float2(h2[j]);
                    o[2*j] += hf.x; o[2*j+1] += hf.y;
                }
            }
        }
    } else {
        int b = i - BT;
        const int* idx = root_nei + (size_t)b*MAX_NB;
        #pragma unroll
        for (int n=0;n<MAX_NB;n++){
            uint4 hr = __ldcg((const uint4*)(g_pairh + (size_t)idx[n]*PW + c8));
            const __nv_bfloat162* h2 = (const __nv_bfloat162*)&hr;
            #pragma unroll
            for (int j=0;j<4;j++){
                float2 hf = __bfloat1622float2(h2[j]);
                o[2*j] += hf.x; o[2*j+1] += hf.y;
            }
        }
    }
    size_t so = (size_t)i*HH + c8;
    *(float4*)&g_stopO[so]   = make_float4(o[0],o[1],o[2],o[3]);
    *(float4*)&g_stopO[so+4] = make_float4(o[4],o[5],o[6],o[7]);
}

// ---------------- stop loss / acc ----------------
__global__ void k_stoploss(const int* __restrict__ direction, const float* __restrict__ usb)
{
    int i = blockIdx.x*256 + threadIdx.x;
    float li = 0.f, ci = 0.f;
    if (i < NSTOP){
        float s = g_score[i] + usb[0];
        float tgt = (i < BT) ? (float)direction[i] : 0.f;
        float sp = (s > 0.f) ? (s + log1pf(expf(-s))) : log1pf(expf(s));
        li = sp - s*tgt;
        float pred = (s >= 0.f) ? 1.f : 0.f;
        ci = (pred == tgt) ? 1.f : 0.f;
    }
    __shared__ float rl[256], rc[256];
    rl[threadIdx.x]=li; rc[threadIdx.x]=ci;
    __syncthreads();
    for (int st=128; st>0; st>>=1){
        if (threadIdx.x < st){ rl[threadIdx.x]+=rl[threadIdx.x+st]; rc[threadIdx.x]+=rc[threadIdx.x+st]; }
        __syncthreads();
    }
    if (threadIdx.x==0){
        atomicAdd(&g_red[3], rl[0]);
        atomicAdd(&g_red[4], rc[0]);
    }
}

// ---------------- pred head CE / acc over compacted rows ----------------
__global__ void k_ce(const int* __restrict__ target)
{
    int slot = blockIdx.x;
    if (slot >= g_cnt) return;
    int i = g_list[slot];
    int t = threadIdx.x;
    const float* S = g_predS + (size_t)slot*VV;
    float val[4];
    float lmax = -1e30f; int lidx = 0;
    #pragma unroll
    for (int r=0;r<4;r++){
        int v = t + 256*r;
        if (v < VV){
            float x = S[v];
            val[r] = x;
            if (x > lmax){ lmax = x; lidx = v; }
        } else val[r] = -1e30f;
    }
    __shared__ float smax[256]; __shared__ int sidx[256];
    smax[t]=lmax; sidx[t]=lidx;
    __syncthreads();
    for (int st=128; st>0; st>>=1){
        if (t < st){
            float o = smax[t+st]; int oi = sidx[t+st];
            if (o > smax[t] || (o == smax[t] && oi < sidx[t])){ smax[t]=o; sidx[t]=oi; }
        }
        __syncthreads();
    }
    float m = smax[0]; int am = sidx[0];
    __syncthreads();
    float se = 0.f;
    #pragma unroll
    for (int r=0;r<4;r++){
        int v = t + 256*r;
        if (v < VV) se += expf(val[r] - m);
    }
    __shared__ float ssum[256];
    ssum[t]=se;
    __syncthreads();
    for (int st=128; st>0; st>>=1){
        if (t < st) ssum[t]+=ssum[t+st];
        __syncthreads();
    }
    if (t==0){
        float lse = m + logf(ssum[0]);
        int tg = target[i];
        float ce = lse - S[tg];
        atomicAdd(&g_red[0], ce);
        atomicAdd(&g_red[1], (am==tg) ? 1.f : 0.f);
        atomicAdd(&g_red[2], 1.f);
    }
}

__global__ void k_final(float* out)
{
    out[0] = g_red[0] / (float)BB;
    out[1] = g_red[3] / (float)BB;
    out[2] = g_red[1] / g_red[2];
    out[3] = g_red[4] / (float)NSTOP;
}

// ---------------- host launch ----------------
extern "C" void kernel_launch(void* const* d_in, const int* in_sizes, int n_in,
                              void* d_out, int out_size)
{
    const float* node_rep = (const float*)d_in[0];
    const int*   clique   = (const int*)  d_in[1];
    const int*   rclique  = (const int*)  d_in[2];
    const int*   nei_h    = (const int*)  d_in[3];
    const int*   nei_o    = (const int*)  d_in[4];
    const int*   rnei     = (const int*)  d_in[5];
    const int*   dir      = (const int*)  d_in[6];
    const int*   ptgt     = (const int*)  d_in[7];
    const float* Wz  = (const float*)d_in[8];
    const float* Wzb = (const float*)d_in[9];
    const float* Wr  = (const float*)d_in[10];
    const float* Wrb = (const float*)d_in[11];
    const float* Ur  = (const float*)d_in[12];
    const float* Wh  = (const float*)d_in[13];
    const float* Whb = (const float*)d_in[14];
    const float* Ww  = (const float*)d_in[15];
    const float* Wwb = (const float*)d_in[16];
    const float* Uw  = (const float*)d_in[17];
    const float* Ub  = (const float*)d_in[18];
    const float* Wo  = (const float*)d_in[19];
    const float* Wob = (const float*)d_in[20];
    const float* Us  = (const float*)d_in[21];
    const float* Usb = (const float*)d_in[22];

    void *pairh;
    float *hfp, *nZ, *nR, *nH, *nS, *stopO, *stopX, *predH, *predS, *score, *red;
    unsigned* bar; int* cnt;
    cudaGetSymbolAddress(&pairh, g_pairh);
    cudaGetSymbolAddress((void**)&hfp,   g_hfp);
    cudaGetSymbolAddress((void**)&nZ,    g_nodeZ);
    cudaGetSymbolAddress((void**)&nR,    g_nodeR);
    cudaGetSymbolAddress((void**)&nH,    g_nodeH);
    cudaGetSymbolAddress((void**)&nS,    g_nodeS);
    cudaGetSymbolAddress((void**)&stopO, g_stopO);
    cudaGetSymbolAddress((void**)&stopX, g_stopX);
    cudaGetSymbolAddress((void**)&predH, g_predH);
    cudaGetSymbolAddress((void**)&predS, g_predS);
    cudaGetSymbolAddress((void**)&score, g_score);
    cudaGetSymbolAddress((void**)&red,   g_red);
    cudaGetSymbolAddress((void**)&bar,   g_bar);
    cudaGetSymbolAddress((void**)&cnt,   g_cnt);

    static int attr_set = 0;
    if (!attr_set){
        cudaFuncSetAttribute(k_scan, cudaFuncAttributeMaxDynamicSharedMemorySize, SMEM_SCAN);
        cudaFuncSetAttribute(tgemm<3,false,true,0>,  cudaFuncAttributeMaxDynamicSharedMemorySize, SMEM_TG);
        cudaFuncSetAttribute(tgemm<2,false,false,0>, cudaFuncAttributeMaxDynamicSharedMemorySize, SMEM_TG);
        cudaFuncSetAttribute(tgemm<1,false,false,1>, cudaFuncAttributeMaxDynamicSharedMemorySize, SMEM_TG);
        cudaFuncSetAttribute(tgemm<0,true,false,2>,  cudaFuncAttributeMaxDynamicSharedMemorySize, SMEM_TG);
        attr_set = 1;
    }

    cudaMemsetAsync(pairh, 0, sizeof(__nv_bfloat16)*(size_t)NMSG*PW);
    cudaMemsetAsync(score, 0, sizeof(float)*NSTOP);
    cudaMemsetAsync(red,   0, sizeof(float)*8);
    cudaMemsetAsync(bar,   0, sizeof(unsigned));
    cudaMemsetAsync(cnt,   0, sizeof(int));

    // Ur transpose+convert, node-level projections, X gathers, compaction
    k_prep<<<dim3(16,16), 256>>>(Ur);
    dim3 gN(4, (BB*N_AT)/128, 4);
    tgemm<3,false,true,0><<<gN, 256, SMEM_TG>>>(node_rep, HH, Wz, HH, nullptr, nZ, HH,
                                                HH, HH, nullptr, nullptr,
                                                Wr, Wh, Uw, nR, nH, nS);
    k_xproj<<<BT, 256>>>(clique, Wzb, Wrb, Whb);
    k_rootS<<<BB, 128>>>(rclique);
    k_compact<<<BT/256, 256>>>(dir);

    // sequential scan (bf16)
    const float* Wzh = Wz + (size_t)HH*HH;
    const float* Whh = Wh + (size_t)HH*HH;
    k_scan<<<NBLK, 256, SMEM_SCAN>>>(nei_h, Wzh, Whh);

    // stop head
    k_oall<<<NSTOP, 64>>>(nei_o, rnei);
    tgemm<2,false,false,0><<<dim3(4, NSTOP/128), 256, SMEM_TG>>>(stopO, HH,
        Uw + (size_t)HH*HH, HH, Ub, nullptr, 0, HH, HH, Us, stopX,
        nullptr, nullptr, nullptr, nullptr, nullptr, nullptr);
    k_stoploss<<<NSTOP/256, 256>>>(dir, Usb);

    // pred head over compacted rows (A = fp32 h copy)
    tgemm<1,false,false,1><<<dim3(4, BT/128), 256, SMEM_TG>>>(hfp, HH, Ww, HH, Wwb,
        predH, HH, HH, HH, nullptr, nullptr,
        nullptr, nullptr, nullptr, nullptr, nullptr, nullptr);
    tgemm<0,true,false,2><<<dim3(7, BT/128), 256, SMEM_TG>>>(predH, HH, Wo, VV, Wob,
        predS, VV, VV, HH, nullptr, nullptr,
        nullptr, nullptr, nullptr, nullptr, nullptr, nullptr);
    k_ce<<<BT, 256>>>(ptgt);

    k_final<<<1,1>>>((float*)d_out);
}